// round 3
// baseline (speedup 1.0000x reference)
#include <cuda_runtime.h>
#include <math.h>

#define TT 512
#define DD 512
#define NBATCH 2
#define VV 256
#define MMEM 256
#define BT 1024
#define D3 1536
#define GRU_BLOCKS 128

// ---------------- static device scratch ----------------
__device__ float g_table[VV * D3];
__device__ float g_pf[BT * DD];
__device__ float g_ps[BT * DD];
__device__ float g_gislow[BT * D3];
__device__ float g_qkv[BT * D3];
__device__ float g_S[NBATCH * TT * TT];
__device__ float g_den[BT];
__device__ float g_attn[BT * MMEM];
__device__ float g_comb[BT * 2048];
__device__ float g_tpre[BT * DD];
__device__ float g_gatepre[BT * DD];
__device__ float g_qh[BT * DD];
__device__ float g_sw[VV * DD];
__device__ float g_h[3][NBATCH * DD];
__device__ unsigned g_bar;

// ---------------- block reductions ----------------
__device__ __forceinline__ float block_red_sum(float v, float* sb) {
    __syncthreads();
    int lane = threadIdx.x & 31, w = threadIdx.x >> 5;
    #pragma unroll
    for (int o = 16; o; o >>= 1) v += __shfl_xor_sync(0xffffffffu, v, o);
    if (lane == 0) sb[w] = v;
    __syncthreads();
    float r = (lane < (int)(blockDim.x >> 5)) ? sb[lane] : 0.f;
    #pragma unroll
    for (int o = 16; o; o >>= 1) r += __shfl_xor_sync(0xffffffffu, r, o);
    return r;
}

__device__ __forceinline__ float block_red_max(float v, float* sb) {
    __syncthreads();
    int lane = threadIdx.x & 31, w = threadIdx.x >> 5;
    #pragma unroll
    for (int o = 16; o; o >>= 1) v = fmaxf(v, __shfl_xor_sync(0xffffffffu, v, o));
    if (lane == 0) sb[w] = v;
    __syncthreads();
    float r = (lane < (int)(blockDim.x >> 5)) ? sb[lane] : -3.4e38f;
    #pragma unroll
    for (int o = 16; o; o >>= 1) r = fmaxf(r, __shfl_xor_sync(0xffffffffu, r, o));
    return r;
}

// ---------------- global barrier (monotonic counter) ----------------
__device__ __forceinline__ void grid_bar(unsigned no) {
    __syncthreads();
    if (threadIdx.x == 0) {
        __threadfence();
        atomicAdd(&g_bar, 1u);
        unsigned target = no * GRU_BLOCKS;
        unsigned v;
        do {
            asm volatile("ld.acquire.gpu.u32 %0, [%1];" : "=r"(v) : "l"(&g_bar) : "memory");
        } while (v < target);
    }
    __syncthreads();
}

// ---------------- persistent GRU: 128 blocks x 4 hidden units ----------------
__global__ void __launch_bounds__(256) gru_kernel(
    const float* __restrict__ whh, const float* __restrict__ bhh,
    const float* __restrict__ gi_table, const int* __restrict__ toks,
    const float* __restrict__ gi_dense, const float* __restrict__ h0,
    float* __restrict__ y, float* __restrict__ y2, float* __restrict__ hT)
{
    __shared__ float ws[12][DD];
    const int tid = threadIdx.x;
    const int ibase = blockIdx.x * 4;

    for (int idx = tid; idx < 1536; idx += 256) {
        int r = idx >> 7;
        int c = (idx & 127) << 2;
        int g = r >> 2, il = r & 3;
        *(float4*)&ws[r][c] = *(const float4*)&whh[(size_t)(g * DD + ibase + il) * DD + c];
    }

    const int w = tid >> 5, lane = tid & 31;
    const int b = w >> 2, il = w & 3;
    const int i = ibase + il;
    const float bh_r = bhh[i], bh_z = bhh[DD + i], bh_n = bhh[2 * DD + i];

    if (lane == 0) g_h[0][b * DD + i] = h0[b * DD + i];
    grid_bar(1u);

    for (int t = 0; t < TT; t++) {
        const int cur = t % 3, nxt = (t + 1) % 3;
        const float* hb = &g_h[cur][b * DD];

        float4 hv[4];
        #pragma unroll
        for (int j = 0; j < 4; j++)
            hv[j] = __ldcg((const float4*)(hb + lane * 4 + j * 128));

        float ar = 0.f, az = 0.f, an = 0.f;
        const int rR = il, rZ = 4 + il, rN = 8 + il;
        #pragma unroll
        for (int j = 0; j < 4; j++) {
            const float4 h4 = hv[j];
            const float4 wr = *(const float4*)&ws[rR][lane * 4 + j * 128];
            const float4 wz = *(const float4*)&ws[rZ][lane * 4 + j * 128];
            const float4 wn = *(const float4*)&ws[rN][lane * 4 + j * 128];
            ar = fmaf(wr.x, h4.x, fmaf(wr.y, h4.y, fmaf(wr.z, h4.z, fmaf(wr.w, h4.w, ar))));
            az = fmaf(wz.x, h4.x, fmaf(wz.y, h4.y, fmaf(wz.z, h4.z, fmaf(wz.w, h4.w, az))));
            an = fmaf(wn.x, h4.x, fmaf(wn.y, h4.y, fmaf(wn.z, h4.z, fmaf(wn.w, h4.w, an))));
        }
        #pragma unroll
        for (int o = 16; o; o >>= 1) {
            ar += __shfl_xor_sync(0xffffffffu, ar, o);
            az += __shfl_xor_sync(0xffffffffu, az, o);
            an += __shfl_xor_sync(0xffffffffu, an, o);
        }

        if (lane == 0) {
            const int row = b * TT + t;
            const float* gi = toks ? (gi_table + (size_t)toks[row] * D3)
                                   : (gi_dense + (size_t)row * D3);
            float gr = gi[i], gz = gi[DD + i], gn = gi[2 * DD + i];
            float hprev = __ldcg(hb + i);
            float r = 1.f / (1.f + expf(-(gr + ar + bh_r)));
            float z = 1.f / (1.f + expf(-(gz + az + bh_z)));
            float n = tanhf(gn + r * (an + bh_n));
            float hn = (1.f - z) * n + z * hprev;
            g_h[nxt][b * DD + i] = hn;
            y[(size_t)row * DD + i] = hn;
            if (y2) y2[(size_t)row * 2048 + i] = hn;
            if (t == TT - 1) hT[b * DD + i] = hn;
        }
        grid_bar((unsigned)(t + 2));
    }
}

__global__ void reset_bar_kernel() { g_bar = 0u; }

// ---------------- generic tiled GEMM ----------------
// TB=true : Bm stored [N,K]  (C = A @ Bm^T);  TB=false: Bm stored [K,N]
template <bool TB, bool CAUSAL>
__global__ void __launch_bounds__(256) gemm_kernel(
    const float* __restrict__ A, const float* __restrict__ Bm,
    const float* __restrict__ bias, float* __restrict__ C,
    int M, int N, int K, int lda, int ldb, int ldc,
    long long sA, long long sB, long long sC, float scale)
{
    __shared__ __align__(16) float As[16][68];
    __shared__ __align__(16) float Bs[16][68];
    const int z = blockIdx.z;
    A += (size_t)z * sA; Bm += (size_t)z * sB; C += (size_t)z * sC;
    const int m0 = blockIdx.y * 64, n0 = blockIdx.x * 64;
    const int tid = threadIdx.x;
    const int lr = tid >> 2, lc = (tid & 3) << 2;
    const int ty = tid >> 4, tx = tid & 15;
    float acc[4][4] = {};
    for (int k0 = 0; k0 < K; k0 += 16) {
        float4 av = *(const float4*)(A + (size_t)(m0 + lr) * lda + k0 + lc);
        As[lc + 0][lr] = av.x; As[lc + 1][lr] = av.y;
        As[lc + 2][lr] = av.z; As[lc + 3][lr] = av.w;
        if (TB) {
            float4 bv = *(const float4*)(Bm + (size_t)(n0 + lr) * ldb + k0 + lc);
            Bs[lc + 0][lr] = bv.x; Bs[lc + 1][lr] = bv.y;
            Bs[lc + 2][lr] = bv.z; Bs[lc + 3][lr] = bv.w;
        } else {
            const int br = tid >> 4, bc = (tid & 15) << 2;
            *(float4*)&Bs[br][bc] = *(const float4*)(Bm + (size_t)(k0 + br) * ldb + n0 + bc);
        }
        __syncthreads();
        #pragma unroll
        for (int k = 0; k < 16; k++) {
            float4 a  = *(const float4*)&As[k][ty << 2];
            float4 b4 = *(const float4*)&Bs[k][tx << 2];
            float af[4] = {a.x, a.y, a.z, a.w};
            float bf[4] = {b4.x, b4.y, b4.z, b4.w};
            #pragma unroll
            for (int ii = 0; ii < 4; ii++)
                #pragma unroll
                for (int jj = 0; jj < 4; jj++)
                    acc[ii][jj] = fmaf(af[ii], bf[jj], acc[ii][jj]);
        }
        __syncthreads();
    }
    const int mm = m0 + (ty << 2), nn = n0 + (tx << 2);
    #pragma unroll
    for (int ii = 0; ii < 4; ii++) {
        #pragma unroll
        for (int jj = 0; jj < 4; jj++) {
            float c = acc[ii][jj] * scale;
            if (bias) c += bias[nn + jj];
            if (CAUSAL && (nn + jj) > (mm + ii)) c = 0.f;
            C[(size_t)(mm + ii) * ldc + nn + jj] = c;
        }
    }
}

// ---------------- small kernels ----------------
__global__ void elu_qk_kernel() {
    int idx = blockIdx.x * blockDim.x + threadIdx.x;
    if (idx >= BT * 1024) return;
    int row = idx >> 10, c = idx & 1023;
    float* p = &g_qkv[(size_t)row * D3 + c];
    float x = *p;
    *p = x > 0.f ? x + 1.f : expf(x);
}

__global__ void den_kernel() {
    __shared__ float sb[32];
    int row = blockIdx.x;
    float s = 0.f;
    for (int c = threadIdx.x; c < TT; c += 256) s += g_S[(size_t)row * TT + c];
    s = block_red_sum(s, sb);
    if (threadIdx.x == 0) g_den[row] = s;
}

__global__ void div_kernel() {
    int idx = blockIdx.x * blockDim.x + threadIdx.x;
    if (idx >= BT * DD) return;
    int row = idx >> 9, j = idx & 511;
    g_comb[(size_t)row * 2048 + 1024 + j] /= (g_den[row] + 1e-6f);
}

__global__ void softmax_kernel() {
    __shared__ float sb[32];
    int row = blockIdx.x;
    float x = g_attn[(size_t)row * MMEM + threadIdx.x];
    float m = block_red_max(x, sb);
    float e = expf(x - m);
    float s = block_red_sum(e, sb);
    g_attn[(size_t)row * MMEM + threadIdx.x] = e / s;
}

// mode 0: out = tanh(LN(in));  mode 1: out = LN(tanh(in))
__global__ void ln_kernel(const float* __restrict__ in, const float* __restrict__ gg,
                          const float* __restrict__ bb, float* __restrict__ out,
                          int ldo, int mode)
{
    __shared__ float sb[32];
    int row = blockIdx.x, tid = threadIdx.x;
    float x0 = in[(size_t)row * DD + tid];
    float x1 = in[(size_t)row * DD + 256 + tid];
    if (mode == 1) { x0 = tanhf(x0); x1 = tanhf(x1); }
    float s  = block_red_sum(x0 + x1, sb);
    float sq = block_red_sum(x0 * x0 + x1 * x1, sb);
    float mean = s * (1.f / 512.f);
    float var  = sq * (1.f / 512.f) - mean * mean;
    float rstd = rsqrtf(var + 1e-5f);
    float y0 = (x0 - mean) * rstd * gg[tid] + bb[tid];
    float y1 = (x1 - mean) * rstd * gg[256 + tid] + bb[256 + tid];
    if (mode == 0) { y0 = tanhf(y0); y1 = tanhf(y1); }
    out[(size_t)row * ldo + tid] = y0;
    out[(size_t)row * ldo + 256 + tid] = y1;
}

__global__ void rownorm_kernel(const float* __restrict__ src) {
    __shared__ float sb[32];
    int row = blockIdx.x, tid = threadIdx.x;
    float x0 = src[(size_t)row * DD + tid];
    float x1 = src[(size_t)row * DD + 256 + tid];
    float ss = block_red_sum(x0 * x0 + x1 * x1, sb);
    float inv = 1.f / fmaxf(sqrtf(ss), 1e-12f);
    g_sw[(size_t)row * DD + tid] = x0 * inv;
    g_sw[(size_t)row * DD + 256 + tid] = x1 * inv;
}

// ---------------- host ----------------
static inline void gemm(const float* A, const float* B, const float* bias, float* C,
                        int M, int N, int K, int lda, int ldb, int ldc,
                        float scale, int batch, long long sA, long long sB, long long sC,
                        bool tb, bool causal)
{
    dim3 grid(N / 64, M / 64, batch);
    if (tb) {
        if (causal)
            gemm_kernel<true, true><<<grid, 256>>>(A, B, bias, C, M, N, K, lda, ldb, ldc, sA, sB, sC, scale);
        else
            gemm_kernel<true, false><<<grid, 256>>>(A, B, bias, C, M, N, K, lda, ldb, ldc, sA, sB, sC, scale);
    } else {
        gemm_kernel<false, false><<<grid, 256>>>(A, B, bias, C, M, N, K, lda, ldb, ldc, sA, sB, sC, scale);
    }
}

extern "C" void kernel_launch(void* const* d_in, const int* in_sizes, int n_in,
                              void* d_out, int out_size)
{
    (void)in_sizes; (void)n_in; (void)out_size;
    const int*   x        = (const int*)d_in[0];
    const float* h_f      = (const float*)d_in[1];
    const float* h_s      = (const float*)d_in[2];
    const float* soma_w   = (const float*)d_in[3];
    const float* fast_wih = (const float*)d_in[4];
    const float* fast_whh = (const float*)d_in[5];
    const float* fast_bih = (const float*)d_in[6];
    const float* fast_bhh = (const float*)d_in[7];
    const float* slow_wih = (const float*)d_in[8];
    const float* slow_whh = (const float*)d_in[9];
    const float* slow_bih = (const float*)d_in[10];
    const float* slow_bhh = (const float*)d_in[11];
    const float* qkv_w    = (const float*)d_in[12];
    const float* qkv_b    = (const float*)d_in[13];
    const float* gate_w   = (const float*)d_in[14];
    const float* gate_b   = (const float*)d_in[15];
    const float* gate_g   = (const float*)d_in[16];
    const float* gate_bb  = (const float*)d_in[17];
    const float* mem_bank = (const float*)d_in[18];
    const float* hip_qw   = (const float*)d_in[19];
    const float* hip_qb   = (const float*)d_in[20];
    const float* axon_w   = (const float*)d_in[21];
    const float* axon_b   = (const float*)d_in[22];
    const float* norm_g   = (const float*)d_in[23];
    const float* norm_b   = (const float*)d_in[24];

    float* out = (float*)d_out;
    float* out_logits  = out;            // [B,T,V]
    float* out_thought = out + 262144;   // [B,T,D]
    float* out_hf      = out + 786432;   // [1,B,D]
    float* out_hs      = out + 787456;   // [1,B,D]

    float *p_table, *p_pf, *p_ps, *p_gislow, *p_qkv, *p_S, *p_attn, *p_comb,
          *p_tpre, *p_gatepre, *p_qh, *p_sw;
    cudaGetSymbolAddress((void**)&p_table,   g_table);
    cudaGetSymbolAddress((void**)&p_pf,      g_pf);
    cudaGetSymbolAddress((void**)&p_ps,      g_ps);
    cudaGetSymbolAddress((void**)&p_gislow,  g_gislow);
    cudaGetSymbolAddress((void**)&p_qkv,     g_qkv);
    cudaGetSymbolAddress((void**)&p_S,       g_S);
    cudaGetSymbolAddress((void**)&p_attn,    g_attn);
    cudaGetSymbolAddress((void**)&p_comb,    g_comb);
    cudaGetSymbolAddress((void**)&p_tpre,    g_tpre);
    cudaGetSymbolAddress((void**)&p_gatepre, g_gatepre);
    cudaGetSymbolAddress((void**)&p_qh,      g_qh);
    cudaGetSymbolAddress((void**)&p_sw,      g_sw);

    // normalized embedding rows for logits
    rownorm_kernel<<<VV, 256>>>(soma_w);

    // fast-GRU input-gate token table: [V,3D] = soma_w @ fast_wih^T + fast_bih
    gemm(soma_w, fast_wih, fast_bih, p_table, 256, 1536, 512, 512, 512, 1536,
         1.f, 1, 0, 0, 0, true, false);

    // fast GRU -> p_f, combined[:, 0:512], hf1
    gru_kernel<<<GRU_BLOCKS, 256>>>(fast_whh, fast_bhh, p_table, x, nullptr,
                                    h_f, p_pf, p_comb, out_hf);
    reset_bar_kernel<<<1, 1>>>();

    // slow-GRU input gates: p_f @ slow_wih^T + slow_bih
    gemm(p_pf, slow_wih, slow_bih, p_gislow, 1024, 1536, 512, 512, 512, 1536,
         1.f, 1, 0, 0, 0, true, false);

    // slow GRU -> p_s, hs1
    gru_kernel<<<GRU_BLOCKS, 256>>>(slow_whh, slow_bhh, nullptr, nullptr, p_gislow,
                                    h_s, p_ps, nullptr, out_hs);
    reset_bar_kernel<<<1, 1>>>();

    // projections from p_s
    gemm(p_ps, qkv_w,  qkv_b,  p_qkv,     1024, 1536, 512, 512, 512, 1536, 1.f, 1, 0, 0, 0, true, false);
    gemm(p_ps, gate_w, gate_b, p_gatepre, 1024,  512, 512, 512, 512,  512, 1.f, 1, 0, 0, 0, true, false);
    gemm(p_ps, hip_qw, hip_qb, p_qh,      1024,  512, 512, 512, 512,  512, 1.f, 1, 0, 0, 0, true, false);

    // q,k <- elu+1
    elu_qk_kernel<<<(BT * 1024) / 256, 256>>>();

    // linear attention == causal attention: S = q k^T (masked), per batch
    gemm(p_qkv, p_qkv + 512, nullptr, p_S, 512, 512, 512, 1536, 1536, 512,
         1.f, 2, 512LL * 1536, 512LL * 1536, 512LL * 512, true, true);
    den_kernel<<<BT, 256>>>();
    // num = S @ v -> combined[:, 1024:1536]
    gemm(p_S, p_qkv + 1024, nullptr, p_comb + 1024, 512, 512, 512, 512, 1536, 2048,
         1.f, 2, 512LL * 512, 512LL * 1536, 512LL * 2048, false, false);
    div_kernel<<<(BT * DD) / 256, 256>>>();

    // intent = tanh(LN(gatepre)) -> combined[:, 512:1024]
    ln_kernel<<<BT, 256>>>(p_gatepre, gate_g, gate_bb, p_comb + 512, 2048, 0);

    // hippocampus: attn = softmax(qh @ mem^T / sqrt(D)); episodes = attn @ mem
    gemm(p_qh, mem_bank, nullptr, p_attn, 1024, 256, 512, 512, 512, 256,
         0.044194173824159216f, 1, 0, 0, 0, true, false);  // 1/sqrt(512)
    softmax_kernel<<<BT, 256>>>();
    gemm(p_attn, mem_bank, nullptr, p_comb + 1536, 1024, 512, 256, 256, 512, 2048,
         1.f, 1, 0, 0, 0, false, false);

    // thought = LN(tanh(combined @ axon_w^T + axon_b))
    gemm(p_comb, axon_w, axon_b, p_tpre, 1024, 512, 2048, 2048, 2048, 512,
         1.f, 1, 0, 0, 0, true, false);
    ln_kernel<<<BT, 256>>>(p_tpre, norm_g, norm_b, out_thought, 512, 1);

    // logits = (thought @ sw^T) * 16
    gemm(out_thought, p_sw, nullptr, out_logits, 1024, 256, 512, 512, 512, 256,
         16.f, 1, 0, 0, 0, true, false);
}

// round 4
// speedup vs baseline: 1.1825x; 1.1825x over previous
#include <cuda_runtime.h>
#include <math.h>

#define TT 512
#define DD 512
#define NBATCH 2
#define VV 256
#define MMEM 256
#define BT 1024
#define D3 1536
#define FUSE_BLOCKS 64
#define UNITS 8

// ---------------- static device scratch ----------------
__device__ float g_table[VV * D3];
__device__ float g_pf[BT * DD];
__device__ float g_ps[BT * DD];
__device__ float g_qkv[BT * D3];
__device__ float g_S[NBATCH * TT * TT];
__device__ float g_den[BT];
__device__ float g_attn[BT * MMEM];
__device__ float g_comb[BT * 2048];
__device__ float g_tpre[BT * DD];
__device__ float g_gatepre[BT * DD];
__device__ float g_qh[BT * DD];
__device__ float g_sw[VV * DD];
__device__ float g_hf3[3][NBATCH * DD];
__device__ float g_hs3[3][NBATCH * DD];
__device__ unsigned g_bar;

// ---------------- block reductions ----------------
__device__ __forceinline__ float block_red_sum(float v, float* sb) {
    __syncthreads();
    int lane = threadIdx.x & 31, w = threadIdx.x >> 5;
    #pragma unroll
    for (int o = 16; o; o >>= 1) v += __shfl_xor_sync(0xffffffffu, v, o);
    if (lane == 0) sb[w] = v;
    __syncthreads();
    float r = (lane < (int)(blockDim.x >> 5)) ? sb[lane] : 0.f;
    #pragma unroll
    for (int o = 16; o; o >>= 1) r += __shfl_xor_sync(0xffffffffu, r, o);
    return r;
}

__device__ __forceinline__ float block_red_max(float v, float* sb) {
    __syncthreads();
    int lane = threadIdx.x & 31, w = threadIdx.x >> 5;
    #pragma unroll
    for (int o = 16; o; o >>= 1) v = fmaxf(v, __shfl_xor_sync(0xffffffffu, v, o));
    if (lane == 0) sb[w] = v;
    __syncthreads();
    float r = (lane < (int)(blockDim.x >> 5)) ? sb[lane] : -3.4e38f;
    #pragma unroll
    for (int o = 16; o; o >>= 1) r = fmaxf(r, __shfl_xor_sync(0xffffffffu, r, o));
    return r;
}

// ---------------- global barrier among FUSE_BLOCKS blocks ----------------
__device__ __forceinline__ void grid_bar(unsigned no) {
    __syncthreads();
    if (threadIdx.x == 0) {
        asm volatile("red.release.gpu.global.add.u32 [%0], 1;" :: "l"(&g_bar) : "memory");
        unsigned target = no * FUSE_BLOCKS;
        unsigned v;
        do {
            asm volatile("ld.acquire.gpu.u32 %0, [%1];" : "=r"(v) : "l"(&g_bar) : "memory");
        } while (v < target);
    }
    __syncthreads();
}

__global__ void reset_bar_kernel() { g_bar = 0u; }

__device__ __forceinline__ float sigf(float x) { return 1.f / (1.f + expf(-x)); }

// ---------------- fused pipelined GRU (fast step t + slow step t-1) ----------------
// 64 blocks x 512 threads, 8 hidden units per block, all weights in smem.
extern __shared__ float smw[];   // [72][512]: 0..23 fast_whh, 24..47 slow_wih, 48..71 slow_whh

__global__ void __launch_bounds__(512) fused_gru_kernel(
    const float* __restrict__ fast_whh, const float* __restrict__ fast_bhh,
    const float* __restrict__ slow_wih, const float* __restrict__ slow_bih,
    const float* __restrict__ slow_whh, const float* __restrict__ slow_bhh,
    const float* __restrict__ gi_table, const int* __restrict__ toks,
    const float* __restrict__ hf0, const float* __restrict__ hs0,
    float* __restrict__ pf, float* __restrict__ comb, float* __restrict__ ps,
    float* __restrict__ hfT, float* __restrict__ hsT)
{
    const int tid = threadIdx.x;
    const int ibase = blockIdx.x * UNITS;

    // load 72 rows x 512 weights (9216 float4, 18 iters @ 512 threads)
    for (int idx = tid; idx < 72 * 128; idx += 512) {
        int r = idx >> 7, c = (idx & 127) << 2;
        int sr = (r < 24) ? r : ((r < 48) ? r - 24 : r - 48);
        int g = sr >> 3, il = sr & 7;
        const float* W = (r < 24) ? fast_whh : ((r < 48) ? slow_wih : slow_whh);
        *(float4*)&smw[r * DD + c] = *(const float4*)&W[(size_t)(g * DD + ibase + il) * DD + c];
    }

    const int w = tid >> 5, lane = tid & 31;
    const int b = w >> 3, il = w & 7;
    const int i = ibase + il;

    const float fb_r  = fast_bhh[i], fb_z  = fast_bhh[DD + i], fb_n  = fast_bhh[2 * DD + i];
    const float sbi_r = slow_bih[i], sbi_z = slow_bih[DD + i], sbi_n = slow_bih[2 * DD + i];
    const float sbh_r = slow_bhh[i], sbh_z = slow_bhh[DD + i], sbh_n = slow_bhh[2 * DD + i];

    if (lane == 0) {
        g_hf3[0][b * DD + i] = hf0[b * DD + i];
        g_hs3[0][b * DD + i] = hs0[b * DD + i];
    }
    grid_bar(1u);

    const int rF0 = il, rF1 = 8 + il, rF2 = 16 + il;
    const int rI0 = 24 + il, rI1 = 32 + il, rI2 = 40 + il;
    const int rH0 = 48 + il, rH1 = 56 + il, rH2 = 64 + il;

    for (int t = 0; t <= TT; t++) {
        const int cur = t % 3, nxt = (t + 1) % 3;       // fast buffers
        // slow buffers for step ts=t-1: reads (t-1)%3 == writes at t-1's nxt? no:
        // slow state for step ts uses cur_s=(t-1)%3, writes nxt_s=t%3.
        const int cur_s = (t + 2) % 3, nxt_s = t % 3;

        float4 hfv[4], hsv[4], pfv[4];
        {
            const float* hfb = &g_hf3[cur][b * DD];
            const float* hsb = &g_hs3[cur_s][b * DD];
            const int prow = b * TT + ((t > 0) ? (t - 1) : 0);
            const float* pfb = pf + (size_t)prow * DD;
            #pragma unroll
            for (int j = 0; j < 4; j++) {
                hfv[j] = __ldcg((const float4*)(hfb + lane * 4 + j * 128));
                hsv[j] = __ldcg((const float4*)(hsb + lane * 4 + j * 128));
                pfv[j] = __ldcg((const float4*)(pfb + lane * 4 + j * 128));
            }
        }

        float fr = 0.f, fz = 0.f, fn = 0.f;
        float ir = 0.f, iz = 0.f, in_ = 0.f;
        float hr = 0.f, hz = 0.f, hn = 0.f;
        #pragma unroll
        for (int j = 0; j < 4; j++) {
            const int c = lane * 4 + j * 128;
            const float4 a = hfv[j], p4 = pfv[j], s4 = hsv[j];
            float4 w0 = *(const float4*)&smw[rF0 * DD + c];
            float4 w1 = *(const float4*)&smw[rF1 * DD + c];
            float4 w2 = *(const float4*)&smw[rF2 * DD + c];
            fr = fmaf(w0.x, a.x, fmaf(w0.y, a.y, fmaf(w0.z, a.z, fmaf(w0.w, a.w, fr))));
            fz = fmaf(w1.x, a.x, fmaf(w1.y, a.y, fmaf(w1.z, a.z, fmaf(w1.w, a.w, fz))));
            fn = fmaf(w2.x, a.x, fmaf(w2.y, a.y, fmaf(w2.z, a.z, fmaf(w2.w, a.w, fn))));
            w0 = *(const float4*)&smw[rI0 * DD + c];
            w1 = *(const float4*)&smw[rI1 * DD + c];
            w2 = *(const float4*)&smw[rI2 * DD + c];
            ir  = fmaf(w0.x, p4.x, fmaf(w0.y, p4.y, fmaf(w0.z, p4.z, fmaf(w0.w, p4.w, ir))));
            iz  = fmaf(w1.x, p4.x, fmaf(w1.y, p4.y, fmaf(w1.z, p4.z, fmaf(w1.w, p4.w, iz))));
            in_ = fmaf(w2.x, p4.x, fmaf(w2.y, p4.y, fmaf(w2.z, p4.z, fmaf(w2.w, p4.w, in_))));
            w0 = *(const float4*)&smw[rH0 * DD + c];
            w1 = *(const float4*)&smw[rH1 * DD + c];
            w2 = *(const float4*)&smw[rH2 * DD + c];
            hr = fmaf(w0.x, s4.x, fmaf(w0.y, s4.y, fmaf(w0.z, s4.z, fmaf(w0.w, s4.w, hr))));
            hz = fmaf(w1.x, s4.x, fmaf(w1.y, s4.y, fmaf(w1.z, s4.z, fmaf(w1.w, s4.w, hz))));
            hn = fmaf(w2.x, s4.x, fmaf(w2.y, s4.y, fmaf(w2.z, s4.z, fmaf(w2.w, s4.w, hn))));
        }
        #pragma unroll
        for (int o = 16; o; o >>= 1) {
            fr += __shfl_xor_sync(0xffffffffu, fr, o);
            fz += __shfl_xor_sync(0xffffffffu, fz, o);
            fn += __shfl_xor_sync(0xffffffffu, fn, o);
            ir += __shfl_xor_sync(0xffffffffu, ir, o);
            iz += __shfl_xor_sync(0xffffffffu, iz, o);
            in_ += __shfl_xor_sync(0xffffffffu, in_, o);
            hr += __shfl_xor_sync(0xffffffffu, hr, o);
            hz += __shfl_xor_sync(0xffffffffu, hz, o);
            hn += __shfl_xor_sync(0xffffffffu, hn, o);
        }

        if (lane == 0) {
            if (t < TT) {   // fast GRU step t
                const int row = b * TT + t;
                const float* gi = gi_table + (size_t)toks[row] * D3;
                float hprev = __ldcg(&g_hf3[cur][b * DD + i]);
                float r = sigf(gi[i] + fr + fb_r);
                float z = sigf(gi[DD + i] + fz + fb_z);
                float n = tanhf(gi[2 * DD + i] + r * (fn + fb_n));
                float hnew = (1.f - z) * n + z * hprev;
                g_hf3[nxt][b * DD + i] = hnew;
                pf[(size_t)row * DD + i] = hnew;
                comb[(size_t)row * 2048 + i] = hnew;
                if (t == TT - 1) hfT[b * DD + i] = hnew;
            }
            if (t >= 1) {   // slow GRU step t-1
                const int ts = t - 1, row = b * TT + ts;
                float hprev = __ldcg(&g_hs3[cur_s][b * DD + i]);
                float r = sigf(ir + sbi_r + hr + sbh_r);
                float z = sigf(iz + sbi_z + hz + sbh_z);
                float n = tanhf(in_ + sbi_n + r * (hn + sbh_n));
                float hnew = (1.f - z) * n + z * hprev;
                g_hs3[nxt_s][b * DD + i] = hnew;
                ps[(size_t)row * DD + i] = hnew;
                if (ts == TT - 1) hsT[b * DD + i] = hnew;
            }
        }
        grid_bar((unsigned)(t + 2));
    }
}

// ---------------- generic tiled GEMM ----------------
// TB=true : Bm stored [N,K]  (C = A @ Bm^T);  TB=false: Bm stored [K,N]
template <bool TB, bool CAUSAL>
__global__ void __launch_bounds__(256) gemm_kernel(
    const float* __restrict__ A, const float* __restrict__ Bm,
    const float* __restrict__ bias, float* __restrict__ C,
    int M, int N, int K, int lda, int ldb, int ldc,
    long long sA, long long sB, long long sC, float scale)
{
    __shared__ __align__(16) float As[16][68];
    __shared__ __align__(16) float Bs[16][68];
    const int z = blockIdx.z;
    A += (size_t)z * sA; Bm += (size_t)z * sB; C += (size_t)z * sC;
    const int m0 = blockIdx.y * 64, n0 = blockIdx.x * 64;
    const int tid = threadIdx.x;
    const int lr = tid >> 2, lc = (tid & 3) << 2;
    const int ty = tid >> 4, tx = tid & 15;
    float acc[4][4] = {};
    for (int k0 = 0; k0 < K; k0 += 16) {
        float4 av = *(const float4*)(A + (size_t)(m0 + lr) * lda + k0 + lc);
        As[lc + 0][lr] = av.x; As[lc + 1][lr] = av.y;
        As[lc + 2][lr] = av.z; As[lc + 3][lr] = av.w;
        if (TB) {
            float4 bv = *(const float4*)(Bm + (size_t)(n0 + lr) * ldb + k0 + lc);
            Bs[lc + 0][lr] = bv.x; Bs[lc + 1][lr] = bv.y;
            Bs[lc + 2][lr] = bv.z; Bs[lc + 3][lr] = bv.w;
        } else {
            const int br = tid >> 4, bc = (tid & 15) << 2;
            *(float4*)&Bs[br][bc] = *(const float4*)(Bm + (size_t)(k0 + br) * ldb + n0 + bc);
        }
        __syncthreads();
        #pragma unroll
        for (int k = 0; k < 16; k++) {
            float4 a  = *(const float4*)&As[k][ty << 2];
            float4 b4 = *(const float4*)&Bs[k][tx << 2];
            float af[4] = {a.x, a.y, a.z, a.w};
            float bf[4] = {b4.x, b4.y, b4.z, b4.w};
            #pragma unroll
            for (int ii = 0; ii < 4; ii++)
                #pragma unroll
                for (int jj = 0; jj < 4; jj++)
                    acc[ii][jj] = fmaf(af[ii], bf[jj], acc[ii][jj]);
        }
        __syncthreads();
    }
    const int mm = m0 + (ty << 2), nn = n0 + (tx << 2);
    #pragma unroll
    for (int ii = 0; ii < 4; ii++) {
        #pragma unroll
        for (int jj = 0; jj < 4; jj++) {
            float c = acc[ii][jj] * scale;
            if (bias) c += bias[nn + jj];
            if (CAUSAL && (nn + jj) > (mm + ii)) c = 0.f;
            C[(size_t)(mm + ii) * ldc + nn + jj] = c;
        }
    }
}

// ---------------- small kernels ----------------
__global__ void elu_qk_kernel() {
    int idx = blockIdx.x * blockDim.x + threadIdx.x;
    if (idx >= BT * 1024) return;
    int row = idx >> 10, c = idx & 1023;
    float* p = &g_qkv[(size_t)row * D3 + c];
    float x = *p;
    *p = x > 0.f ? x + 1.f : expf(x);
}

__global__ void den_kernel() {
    __shared__ float sb[32];
    int row = blockIdx.x;
    float s = 0.f;
    for (int c = threadIdx.x; c < TT; c += 256) s += g_S[(size_t)row * TT + c];
    s = block_red_sum(s, sb);
    if (threadIdx.x == 0) g_den[row] = s;
}

__global__ void div_kernel() {
    int idx = blockIdx.x * blockDim.x + threadIdx.x;
    if (idx >= BT * DD) return;
    int row = idx >> 9, j = idx & 511;
    g_comb[(size_t)row * 2048 + 1024 + j] /= (g_den[row] + 1e-6f);
}

__global__ void softmax_kernel() {
    __shared__ float sb[32];
    int row = blockIdx.x;
    float x = g_attn[(size_t)row * MMEM + threadIdx.x];
    float m = block_red_max(x, sb);
    float e = expf(x - m);
    float s = block_red_sum(e, sb);
    g_attn[(size_t)row * MMEM + threadIdx.x] = e / s;
}

// mode 0: out = tanh(LN(in));  mode 1: out = LN(tanh(in))
__global__ void ln_kernel(const float* __restrict__ in, const float* __restrict__ gg,
                          const float* __restrict__ bb, float* __restrict__ out,
                          int ldo, int mode)
{
    __shared__ float sb[32];
    int row = blockIdx.x, tid = threadIdx.x;
    float x0 = in[(size_t)row * DD + tid];
    float x1 = in[(size_t)row * DD + 256 + tid];
    if (mode == 1) { x0 = tanhf(x0); x1 = tanhf(x1); }
    float s  = block_red_sum(x0 + x1, sb);
    float sq = block_red_sum(x0 * x0 + x1 * x1, sb);
    float mean = s * (1.f / 512.f);
    float var  = sq * (1.f / 512.f) - mean * mean;
    float rstd = rsqrtf(var + 1e-5f);
    float y0 = (x0 - mean) * rstd * gg[tid] + bb[tid];
    float y1 = (x1 - mean) * rstd * gg[256 + tid] + bb[256 + tid];
    if (mode == 0) { y0 = tanhf(y0); y1 = tanhf(y1); }
    out[(size_t)row * ldo + tid] = y0;
    out[(size_t)row * ldo + 256 + tid] = y1;
}

__global__ void rownorm_kernel(const float* __restrict__ src) {
    __shared__ float sb[32];
    int row = blockIdx.x, tid = threadIdx.x;
    float x0 = src[(size_t)row * DD + tid];
    float x1 = src[(size_t)row * DD + 256 + tid];
    float ss = block_red_sum(x0 * x0 + x1 * x1, sb);
    float inv = 1.f / fmaxf(sqrtf(ss), 1e-12f);
    g_sw[(size_t)row * DD + tid] = x0 * inv;
    g_sw[(size_t)row * DD + 256 + tid] = x1 * inv;
}

// ---------------- host ----------------
static inline void gemm(const float* A, const float* B, const float* bias, float* C,
                        int M, int N, int K, int lda, int ldb, int ldc,
                        float scale, int batch, long long sA, long long sB, long long sC,
                        bool tb, bool causal)
{
    dim3 grid(N / 64, M / 64, batch);
    if (tb) {
        if (causal)
            gemm_kernel<true, true><<<grid, 256>>>(A, B, bias, C, M, N, K, lda, ldb, ldc, sA, sB, sC, scale);
        else
            gemm_kernel<true, false><<<grid, 256>>>(A, B, bias, C, M, N, K, lda, ldb, ldc, sA, sB, sC, scale);
    } else {
        gemm_kernel<false, false><<<grid, 256>>>(A, B, bias, C, M, N, K, lda, ldb, ldc, sA, sB, sC, scale);
    }
}

extern "C" void kernel_launch(void* const* d_in, const int* in_sizes, int n_in,
                              void* d_out, int out_size)
{
    (void)in_sizes; (void)n_in; (void)out_size;
    const int*   x        = (const int*)d_in[0];
    const float* h_f      = (const float*)d_in[1];
    const float* h_s      = (const float*)d_in[2];
    const float* soma_w   = (const float*)d_in[3];
    const float* fast_wih = (const float*)d_in[4];
    const float* fast_whh = (const float*)d_in[5];
    const float* fast_bih = (const float*)d_in[6];
    const float* fast_bhh = (const float*)d_in[7];
    const float* slow_wih = (const float*)d_in[8];
    const float* slow_whh = (const float*)d_in[9];
    const float* slow_bih = (const float*)d_in[10];
    const float* slow_bhh = (const float*)d_in[11];
    const float* qkv_w    = (const float*)d_in[12];
    const float* qkv_b    = (const float*)d_in[13];
    const float* gate_w   = (const float*)d_in[14];
    const float* gate_b   = (const float*)d_in[15];
    const float* gate_g   = (const float*)d_in[16];
    const float* gate_bb  = (const float*)d_in[17];
    const float* mem_bank = (const float*)d_in[18];
    const float* hip_qw   = (const float*)d_in[19];
    const float* hip_qb   = (const float*)d_in[20];
    const float* axon_w   = (const float*)d_in[21];
    const float* axon_b   = (const float*)d_in[22];
    const float* norm_g   = (const float*)d_in[23];
    const float* norm_b   = (const float*)d_in[24];

    float* out = (float*)d_out;
    float* out_logits  = out;            // [B,T,V]
    float* out_thought = out + 262144;   // [B,T,D]
    float* out_hf      = out + 786432;   // [1,B,D]
    float* out_hs      = out + 787456;   // [1,B,D]

    float *p_table, *p_pf, *p_ps, *p_qkv, *p_S, *p_attn, *p_comb,
          *p_tpre, *p_gatepre, *p_qh, *p_sw;
    cudaGetSymbolAddress((void**)&p_table,   g_table);
    cudaGetSymbolAddress((void**)&p_pf,      g_pf);
    cudaGetSymbolAddress((void**)&p_ps,      g_ps);
    cudaGetSymbolAddress((void**)&p_qkv,     g_qkv);
    cudaGetSymbolAddress((void**)&p_S,       g_S);
    cudaGetSymbolAddress((void**)&p_attn,    g_attn);
    cudaGetSymbolAddress((void**)&p_comb,    g_comb);
    cudaGetSymbolAddress((void**)&p_tpre,    g_tpre);
    cudaGetSymbolAddress((void**)&p_gatepre, g_gatepre);
    cudaGetSymbolAddress((void**)&p_qh,      g_qh);
    cudaGetSymbolAddress((void**)&p_sw,      g_sw);

    // normalized embedding rows for logits
    rownorm_kernel<<<VV, 256>>>(soma_w);

    // fast-GRU input-gate token table: [V,3D] = soma_w @ fast_wih^T + fast_bih
    gemm(soma_w, fast_wih, fast_bih, p_table, 256, 1536, 512, 512, 512, 1536,
         1.f, 1, 0, 0, 0, true, false);

    // fused pipelined GRUs -> p_f, comb[:,0:512], p_s, hf1, hs1
    static int smem_set = 0;
    if (!smem_set) {
        cudaFuncSetAttribute(fused_gru_kernel,
                             cudaFuncAttributeMaxDynamicSharedMemorySize, 72 * DD * 4);
        smem_set = 1;
    }
    fused_gru_kernel<<<FUSE_BLOCKS, 512, 72 * DD * 4>>>(
        fast_whh, fast_bhh, slow_wih, slow_bih, slow_whh, slow_bhh,
        p_table, x, h_f, h_s, p_pf, p_comb, p_ps, out_hf, out_hs);
    reset_bar_kernel<<<1, 1>>>();

    // projections from p_s
    gemm(p_ps, qkv_w,  qkv_b,  p_qkv,     1024, 1536, 512, 512, 512, 1536, 1.f, 1, 0, 0, 0, true, false);
    gemm(p_ps, gate_w, gate_b, p_gatepre, 1024,  512, 512, 512, 512,  512, 1.f, 1, 0, 0, 0, true, false);
    gemm(p_ps, hip_qw, hip_qb, p_qh,      1024,  512, 512, 512, 512,  512, 1.f, 1, 0, 0, 0, true, false);

    // q,k <- elu+1
    elu_qk_kernel<<<(BT * 1024) / 256, 256>>>();

    // linear attention == causal attention: S = q k^T (masked), per batch
    gemm(p_qkv, p_qkv + 512, nullptr, p_S, 512, 512, 512, 1536, 1536, 512,
         1.f, 2, 512LL * 1536, 512LL * 1536, 512LL * 512, true, true);
    den_kernel<<<BT, 256>>>();
    // num = S @ v -> combined[:, 1024:1536]
    gemm(p_S, p_qkv + 1024, nullptr, p_comb + 1024, 512, 512, 512, 512, 1536, 2048,
         1.f, 2, 512LL * 512, 512LL * 1536, 512LL * 2048, false, false);
    div_kernel<<<(BT * DD) / 256, 256>>>();

    // intent = tanh(LN(gatepre)) -> combined[:, 512:1024]
    ln_kernel<<<BT, 256>>>(p_gatepre, gate_g, gate_bb, p_comb + 512, 2048, 0);

    // hippocampus: attn = softmax(qh @ mem^T / sqrt(D)); episodes = attn @ mem
    gemm(p_qh, mem_bank, nullptr, p_attn, 1024, 256, 512, 512, 512, 256,
         0.044194173824159216f, 1, 0, 0, 0, true, false);
    softmax_kernel<<<BT, 256>>>();
    gemm(p_attn, mem_bank, nullptr, p_comb + 1536, 1024, 512, 256, 256, 512, 2048,
         1.f, 1, 0, 0, 0, false, false);

    // thought = LN(tanh(combined @ axon_w^T + axon_b))
    gemm(p_comb, axon_w, axon_b, p_tpre, 1024, 512, 2048, 2048, 2048, 512,
         1.f, 1, 0, 0, 0, true, false);
    ln_kernel<<<BT, 256>>>(p_tpre, norm_g, norm_b, out_thought, 512, 1);

    // logits = (thought @ sw^T) * 16
    gemm(out_thought, p_sw, nullptr, out_logits, 1024, 256, 512, 512, 512, 256,
         16.f, 1, 0, 0, 0, true, false);
}

// round 5
// speedup vs baseline: 1.2107x; 1.0238x over previous
#include <cuda_runtime.h>
#include <math.h>

#define TT 512
#define DD 512
#define NBATCH 2
#define VV 256
#define MMEM 256
#define BT 1024
#define D3 1536
#define FUSE_BLOCKS 128
#define UNITS 4

// ---------------- static device scratch ----------------
__device__ float g_table[VV * D3];
__device__ float g_pf[BT * DD];
__device__ float g_ps[BT * DD];
__device__ float g_qkv[BT * D3];
__device__ float g_S[NBATCH * TT * TT];
__device__ float g_den[BT];
__device__ float g_attn[BT * MMEM];
__device__ float g_comb[BT * 2048];
__device__ float g_tpre[BT * DD];
__device__ float g_gatepre[BT * DD];
__device__ float g_qh[BT * DD];
__device__ float g_sw[VV * DD];
__device__ float g_hf3[3][NBATCH * DD];
__device__ float g_hs3[3][NBATCH * DD];
__device__ unsigned g_bar;

// ---------------- block reductions ----------------
__device__ __forceinline__ float block_red_sum(float v, float* sb) {
    __syncthreads();
    int lane = threadIdx.x & 31, w = threadIdx.x >> 5;
    #pragma unroll
    for (int o = 16; o; o >>= 1) v += __shfl_xor_sync(0xffffffffu, v, o);
    if (lane == 0) sb[w] = v;
    __syncthreads();
    float r = (lane < (int)(blockDim.x >> 5)) ? sb[lane] : 0.f;
    #pragma unroll
    for (int o = 16; o; o >>= 1) r += __shfl_xor_sync(0xffffffffu, r, o);
    return r;
}

__device__ __forceinline__ float block_red_max(float v, float* sb) {
    __syncthreads();
    int lane = threadIdx.x & 31, w = threadIdx.x >> 5;
    #pragma unroll
    for (int o = 16; o; o >>= 1) v = fmaxf(v, __shfl_xor_sync(0xffffffffu, v, o));
    if (lane == 0) sb[w] = v;
    __syncthreads();
    float r = (lane < (int)(blockDim.x >> 5)) ? sb[lane] : -3.4e38f;
    #pragma unroll
    for (int o = 16; o; o >>= 1) r = fmaxf(r, __shfl_xor_sync(0xffffffffu, r, o));
    return r;
}

// ---------------- global barrier: one arriver/block, per-warp spin ----------------
__device__ __forceinline__ void grid_bar(unsigned no) {
    __syncthreads();
    if (threadIdx.x == 0)
        asm volatile("red.release.gpu.global.add.u32 [%0], 1;" :: "l"(&g_bar) : "memory");
    if ((threadIdx.x & 31) == 0) {
        unsigned target = no * FUSE_BLOCKS;
        unsigned v;
        do {
            asm volatile("ld.acquire.gpu.u32 %0, [%1];" : "=r"(v) : "l"(&g_bar) : "memory");
        } while (v < target);
    }
    __syncwarp();
}

__global__ void reset_bar_kernel() { g_bar = 0u; }

__device__ __forceinline__ float sigf(float x) { return 1.f / (1.f + expf(-x)); }

// extract element idx (0..511) of a distributed h vector (lane l holds cols l*4+j*128)
__device__ __forceinline__ float warp_extract(const float4* v, int idx) {
    int j = idx >> 7, sl = (idx & 127) >> 2, c = idx & 3;
    float4 x = (j == 0) ? v[0] : (j == 1) ? v[1] : (j == 2) ? v[2] : v[3];
    float val = (c == 0) ? x.x : (c == 1) ? x.y : (c == 2) ? x.z : x.w;
    return __shfl_sync(0xffffffffu, val, sl);
}

// ---------------- fused pipelined GRU: 128 blocks x 256 thr, 4 units ----------------
extern __shared__ float smw[];   // [36][512]: 0..11 fast_whh, 12..23 slow_wih, 24..35 slow_whh

__global__ void __launch_bounds__(256) fused_gru_kernel(
    const float* __restrict__ fast_whh, const float* __restrict__ fast_bhh,
    const float* __restrict__ slow_wih, const float* __restrict__ slow_bih,
    const float* __restrict__ slow_whh, const float* __restrict__ slow_bhh,
    const float* __restrict__ gi_table, const int* __restrict__ toks,
    const float* __restrict__ hf0, const float* __restrict__ hs0,
    float* __restrict__ pf, float* __restrict__ comb, float* __restrict__ ps,
    float* __restrict__ hfT, float* __restrict__ hsT)
{
    const int tid = threadIdx.x;
    const int ibase = blockIdx.x * UNITS;

    // load 36 rows x 512 weights (4608 float4, 18 iters @ 256 threads)
    for (int idx = tid; idx < 36 * 128; idx += 256) {
        int r = idx >> 7, c = (idx & 127) << 2;
        int sr = (r < 12) ? r : ((r < 24) ? r - 12 : r - 24);
        int g = sr >> 2, il = sr & 3;
        const float* W = (r < 12) ? fast_whh : ((r < 24) ? slow_wih : slow_whh);
        *(float4*)&smw[r * DD + c] = *(const float4*)&W[(size_t)(g * DD + ibase + il) * DD + c];
    }

    const int w = tid >> 5, lane = tid & 31;
    const int b = w >> 2, il = w & 3;
    const int i = ibase + il;

    const float fb_r  = fast_bhh[i], fb_z  = fast_bhh[DD + i], fb_n  = fast_bhh[2 * DD + i];
    const float sbi_r = slow_bih[i], sbi_z = slow_bih[DD + i], sbi_n = slow_bih[2 * DD + i];
    const float sbh_r = slow_bhh[i], sbh_z = slow_bhh[DD + i], sbh_n = slow_bhh[2 * DD + i];

    if (lane == 0) {
        g_hf3[0][b * DD + i] = hf0[b * DD + i];
        g_hs3[0][b * DD + i] = hs0[b * DD + i];
    }
    grid_bar(1u);

    const int rF0 = il, rF1 = 4 + il, rF2 = 8 + il;
    const int rI0 = 12 + il, rI1 = 16 + il, rI2 = 20 + il;
    const int rH0 = 24 + il, rH1 = 28 + il, rH2 = 32 + il;

    for (int t = 0; t <= TT; t++) {
        const int cur = t % 3, nxt = (t + 1) % 3;
        const int cur_s = (t + 2) % 3, nxt_s = t % 3;

        // prefetch fast-GRU input gates for step t (lane 0)
        float gr = 0.f, gz = 0.f, gn = 0.f;
        if (lane == 0 && t < TT) {
            const int row = b * TT + t;
            const float* gi = gi_table + (size_t)__ldg(&toks[row]) * D3;
            gr = __ldg(gi + i); gz = __ldg(gi + DD + i); gn = __ldg(gi + 2 * DD + i);
        }

        float4 hfv[4], hsv[4], pfv[4];
        {
            const float* hfb = &g_hf3[cur][b * DD];
            const float* hsb = &g_hs3[cur_s][b * DD];
            const int prow = b * TT + ((t > 0) ? (t - 1) : 0);
            const float* pfb = pf + (size_t)prow * DD;
            #pragma unroll
            for (int j = 0; j < 4; j++) {
                hfv[j] = __ldcg((const float4*)(hfb + lane * 4 + j * 128));
                hsv[j] = __ldcg((const float4*)(hsb + lane * 4 + j * 128));
                pfv[j] = __ldcg((const float4*)(pfb + lane * 4 + j * 128));
            }
        }

        float fr = 0.f, fz = 0.f, fn = 0.f;
        float ir = 0.f, iz = 0.f, in_ = 0.f;
        float hr = 0.f, hz = 0.f, hn = 0.f;
        #pragma unroll
        for (int j = 0; j < 4; j++) {
            const int c = lane * 4 + j * 128;
            const float4 a = hfv[j], p4 = pfv[j], s4 = hsv[j];
            float4 w0 = *(const float4*)&smw[rF0 * DD + c];
            float4 w1 = *(const float4*)&smw[rF1 * DD + c];
            float4 w2 = *(const float4*)&smw[rF2 * DD + c];
            fr = fmaf(w0.x, a.x, fmaf(w0.y, a.y, fmaf(w0.z, a.z, fmaf(w0.w, a.w, fr))));
            fz = fmaf(w1.x, a.x, fmaf(w1.y, a.y, fmaf(w1.z, a.z, fmaf(w1.w, a.w, fz))));
            fn = fmaf(w2.x, a.x, fmaf(w2.y, a.y, fmaf(w2.z, a.z, fmaf(w2.w, a.w, fn))));
            w0 = *(const float4*)&smw[rI0 * DD + c];
            w1 = *(const float4*)&smw[rI1 * DD + c];
            w2 = *(const float4*)&smw[rI2 * DD + c];
            ir  = fmaf(w0.x, p4.x, fmaf(w0.y, p4.y, fmaf(w0.z, p4.z, fmaf(w0.w, p4.w, ir))));
            iz  = fmaf(w1.x, p4.x, fmaf(w1.y, p4.y, fmaf(w1.z, p4.z, fmaf(w1.w, p4.w, iz))));
            in_ = fmaf(w2.x, p4.x, fmaf(w2.y, p4.y, fmaf(w2.z, p4.z, fmaf(w2.w, p4.w, in_))));
            w0 = *(const float4*)&smw[rH0 * DD + c];
            w1 = *(const float4*)&smw[rH1 * DD + c];
            w2 = *(const float4*)&smw[rH2 * DD + c];
            hr = fmaf(w0.x, s4.x, fmaf(w0.y, s4.y, fmaf(w0.z, s4.z, fmaf(w0.w, s4.w, hr))));
            hz = fmaf(w1.x, s4.x, fmaf(w1.y, s4.y, fmaf(w1.z, s4.z, fmaf(w1.w, s4.w, hz))));
            hn = fmaf(w2.x, s4.x, fmaf(w2.y, s4.y, fmaf(w2.z, s4.z, fmaf(w2.w, s4.w, hn))));
        }
        #pragma unroll
        for (int o = 16; o; o >>= 1) {
            fr += __shfl_xor_sync(0xffffffffu, fr, o);
            fz += __shfl_xor_sync(0xffffffffu, fz, o);
            fn += __shfl_xor_sync(0xffffffffu, fn, o);
            ir += __shfl_xor_sync(0xffffffffu, ir, o);
            iz += __shfl_xor_sync(0xffffffffu, iz, o);
            in_ += __shfl_xor_sync(0xffffffffu, in_, o);
            hr += __shfl_xor_sync(0xffffffffu, hr, o);
            hz += __shfl_xor_sync(0xffffffffu, hz, o);
            hn += __shfl_xor_sync(0xffffffffu, hn, o);
        }

        // previous states from registers (no extra global load)
        float hf_prev = warp_extract(hfv, i);
        float hs_prev = warp_extract(hsv, i);

        if (lane == 0) {
            if (t < TT) {   // fast GRU step t
                const int row = b * TT + t;
                float r = sigf(gr + fr + fb_r);
                float z = sigf(gz + fz + fb_z);
                float n = tanhf(gn + r * (fn + fb_n));
                float hnew = (1.f - z) * n + z * hf_prev;
                g_hf3[nxt][b * DD + i] = hnew;
                pf[(size_t)row * DD + i] = hnew;
                comb[(size_t)row * 2048 + i] = hnew;
                if (t == TT - 1) hfT[b * DD + i] = hnew;
            }
            if (t >= 1) {   // slow GRU step t-1
                const int ts = t - 1, row = b * TT + ts;
                float r = sigf(ir + sbi_r + hr + sbh_r);
                float z = sigf(iz + sbi_z + hz + sbh_z);
                float n = tanhf(in_ + sbi_n + r * (hn + sbh_n));
                float hnew = (1.f - z) * n + z * hs_prev;
                g_hs3[nxt_s][b * DD + i] = hnew;
                ps[(size_t)row * DD + i] = hnew;
                if (ts == TT - 1) hsT[b * DD + i] = hnew;
            }
        }
        grid_bar((unsigned)(t + 2));
    }
}

// ---------------- double-buffered tiled GEMM ----------------
// TB=true : Bm stored [N,K]  (C = A @ Bm^T);  TB=false: Bm stored [K,N]
template <bool TB, bool CAUSAL>
__global__ void __launch_bounds__(256) gemm_kernel(
    const float* __restrict__ A, const float* __restrict__ Bm,
    const float* __restrict__ bias, float* __restrict__ C,
    int M, int N, int K, int lda, int ldb, int ldc,
    long long sA, long long sB, long long sC, float scale)
{
    __shared__ __align__(16) float As[2][16][68];
    __shared__ __align__(16) float Bs[2][16][68];
    const int z = blockIdx.z;
    A += (size_t)z * sA; Bm += (size_t)z * sB; C += (size_t)z * sC;
    const int m0 = blockIdx.y * 64, n0 = blockIdx.x * 64;
    const int tid = threadIdx.x;
    const int lr = tid >> 2, lc = (tid & 3) << 2;   // TB / A loads
    const int br = tid >> 4, bc = (tid & 15) << 2;  // NN B loads
    const int ty = tid >> 4, tx = tid & 15;

    float4 av = *(const float4*)(A + (size_t)(m0 + lr) * lda + lc);
    float4 bv;
    if (TB) bv = *(const float4*)(Bm + (size_t)(n0 + lr) * ldb + lc);
    else    bv = *(const float4*)(Bm + (size_t)br * ldb + n0 + bc);

    As[0][lc + 0][lr] = av.x; As[0][lc + 1][lr] = av.y;
    As[0][lc + 2][lr] = av.z; As[0][lc + 3][lr] = av.w;
    if (TB) {
        Bs[0][lc + 0][lr] = bv.x; Bs[0][lc + 1][lr] = bv.y;
        Bs[0][lc + 2][lr] = bv.z; Bs[0][lc + 3][lr] = bv.w;
    } else {
        *(float4*)&Bs[0][br][bc] = bv;
    }
    __syncthreads();

    float acc[4][4] = {};
    const int P = K >> 4;
    int buf = 0;
    for (int p = 0; p < P; p++) {
        if (p + 1 < P) {
            const int k0n = (p + 1) << 4;
            av = *(const float4*)(A + (size_t)(m0 + lr) * lda + k0n + lc);
            if (TB) bv = *(const float4*)(Bm + (size_t)(n0 + lr) * ldb + k0n + lc);
            else    bv = *(const float4*)(Bm + (size_t)(k0n + br) * ldb + n0 + bc);
        }
        #pragma unroll
        for (int k = 0; k < 16; k++) {
            float4 a  = *(const float4*)&As[buf][k][ty << 2];
            float4 b4 = *(const float4*)&Bs[buf][k][tx << 2];
            float af[4] = {a.x, a.y, a.z, a.w};
            float bf[4] = {b4.x, b4.y, b4.z, b4.w};
            #pragma unroll
            for (int ii = 0; ii < 4; ii++)
                #pragma unroll
                for (int jj = 0; jj < 4; jj++)
                    acc[ii][jj] = fmaf(af[ii], bf[jj], acc[ii][jj]);
        }
        if (p + 1 < P) {
            const int nb = buf ^ 1;
            As[nb][lc + 0][lr] = av.x; As[nb][lc + 1][lr] = av.y;
            As[nb][lc + 2][lr] = av.z; As[nb][lc + 3][lr] = av.w;
            if (TB) {
                Bs[nb][lc + 0][lr] = bv.x; Bs[nb][lc + 1][lr] = bv.y;
                Bs[nb][lc + 2][lr] = bv.z; Bs[nb][lc + 3][lr] = bv.w;
            } else {
                *(float4*)&Bs[nb][br][bc] = bv;
            }
            __syncthreads();
            buf = nb;
        }
    }

    const int mm = m0 + (ty << 2), nn = n0 + (tx << 2);
    #pragma unroll
    for (int ii = 0; ii < 4; ii++) {
        #pragma unroll
        for (int jj = 0; jj < 4; jj++) {
            float c = acc[ii][jj] * scale;
            if (bias) c += bias[nn + jj];
            if (CAUSAL && (nn + jj) > (mm + ii)) c = 0.f;
            C[(size_t)(mm + ii) * ldc + nn + jj] = c;
        }
    }
}

// ---------------- small kernels ----------------
__global__ void elu_qk_kernel() {
    int idx = blockIdx.x * blockDim.x + threadIdx.x;
    if (idx >= BT * 1024) return;
    int row = idx >> 10, c = idx & 1023;
    float* p = &g_qkv[(size_t)row * D3 + c];
    float x = *p;
    *p = x > 0.f ? x + 1.f : expf(x);
}

__global__ void den_kernel() {
    __shared__ float sb[32];
    int row = blockIdx.x;
    float s = 0.f;
    for (int c = threadIdx.x; c < TT; c += 256) s += g_S[(size_t)row * TT + c];
    s = block_red_sum(s, sb);
    if (threadIdx.x == 0) g_den[row] = s;
}

__global__ void div_kernel() {
    int idx = blockIdx.x * blockDim.x + threadIdx.x;
    if (idx >= BT * DD) return;
    int row = idx >> 9, j = idx & 511;
    g_comb[(size_t)row * 2048 + 1024 + j] /= (g_den[row] + 1e-6f);
}

__global__ void softmax_kernel() {
    __shared__ float sb[32];
    int row = blockIdx.x;
    float x = g_attn[(size_t)row * MMEM + threadIdx.x];
    float m = block_red_max(x, sb);
    float e = expf(x - m);
    float s = block_red_sum(e, sb);
    g_attn[(size_t)row * MMEM + threadIdx.x] = e / s;
}

// mode 0: out = tanh(LN(in));  mode 1: out = LN(tanh(in))
__global__ void ln_kernel(const float* __restrict__ in, const float* __restrict__ gg,
                          const float* __restrict__ bb, float* __restrict__ out,
                          int ldo, int mode)
{
    __shared__ float sb[32];
    int row = blockIdx.x, tid = threadIdx.x;
    float x0 = in[(size_t)row * DD + tid];
    float x1 = in[(size_t)row * DD + 256 + tid];
    if (mode == 1) { x0 = tanhf(x0); x1 = tanhf(x1); }
    float s  = block_red_sum(x0 + x1, sb);
    float sq = block_red_sum(x0 * x0 + x1 * x1, sb);
    float mean = s * (1.f / 512.f);
    float var  = sq * (1.f / 512.f) - mean * mean;
    float rstd = rsqrtf(var + 1e-5f);
    float y0 = (x0 - mean) * rstd * gg[tid] + bb[tid];
    float y1 = (x1 - mean) * rstd * gg[256 + tid] + bb[256 + tid];
    if (mode == 0) { y0 = tanhf(y0); y1 = tanhf(y1); }
    out[(size_t)row * ldo + tid] = y0;
    out[(size_t)row * ldo + 256 + tid] = y1;
}

__global__ void rownorm_kernel(const float* __restrict__ src) {
    __shared__ float sb[32];
    int row = blockIdx.x, tid = threadIdx.x;
    float x0 = src[(size_t)row * DD + tid];
    float x1 = src[(size_t)row * DD + 256 + tid];
    float ss = block_red_sum(x0 * x0 + x1 * x1, sb);
    float inv = 1.f / fmaxf(sqrtf(ss), 1e-12f);
    g_sw[(size_t)row * DD + tid] = x0 * inv;
    g_sw[(size_t)row * DD + 256 + tid] = x1 * inv;
}

// ---------------- host ----------------
static inline void gemm(const float* A, const float* B, const float* bias, float* C,
                        int M, int N, int K, int lda, int ldb, int ldc,
                        float scale, int batch, long long sA, long long sB, long long sC,
                        bool tb, bool causal)
{
    dim3 grid(N / 64, M / 64, batch);
    if (tb) {
        if (causal)
            gemm_kernel<true, true><<<grid, 256>>>(A, B, bias, C, M, N, K, lda, ldb, ldc, sA, sB, sC, scale);
        else
            gemm_kernel<true, false><<<grid, 256>>>(A, B, bias, C, M, N, K, lda, ldb, ldc, sA, sB, sC, scale);
    } else {
        gemm_kernel<false, false><<<grid, 256>>>(A, B, bias, C, M, N, K, lda, ldb, ldc, sA, sB, sC, scale);
    }
}

extern "C" void kernel_launch(void* const* d_in, const int* in_sizes, int n_in,
                              void* d_out, int out_size)
{
    (void)in_sizes; (void)n_in; (void)out_size;
    const int*   x        = (const int*)d_in[0];
    const float* h_f      = (const float*)d_in[1];
    const float* h_s      = (const float*)d_in[2];
    const float* soma_w   = (const float*)d_in[3];
    const float* fast_wih = (const float*)d_in[4];
    const float* fast_whh = (const float*)d_in[5];
    const float* fast_bih = (const float*)d_in[6];
    const float* fast_bhh = (const float*)d_in[7];
    const float* slow_wih = (const float*)d_in[8];
    const float* slow_whh = (const float*)d_in[9];
    const float* slow_bih = (const float*)d_in[10];
    const float* slow_bhh = (const float*)d_in[11];
    const float* qkv_w    = (const float*)d_in[12];
    const float* qkv_b    = (const float*)d_in[13];
    const float* gate_w   = (const float*)d_in[14];
    const float* gate_b   = (const float*)d_in[15];
    const float* gate_g   = (const float*)d_in[16];
    const float* gate_bb  = (const float*)d_in[17];
    const float* mem_bank = (const float*)d_in[18];
    const float* hip_qw   = (const float*)d_in[19];
    const float* hip_qb   = (const float*)d_in[20];
    const float* axon_w   = (const float*)d_in[21];
    const float* axon_b   = (const float*)d_in[22];
    const float* norm_g   = (const float*)d_in[23];
    const float* norm_b   = (const float*)d_in[24];

    float* out = (float*)d_out;
    float* out_logits  = out;            // [B,T,V]
    float* out_thought = out + 262144;   // [B,T,D]
    float* out_hf      = out + 786432;   // [1,B,D]
    float* out_hs      = out + 787456;   // [1,B,D]

    float *p_table, *p_pf, *p_ps, *p_qkv, *p_S, *p_attn, *p_comb,
          *p_tpre, *p_gatepre, *p_qh, *p_sw;
    cudaGetSymbolAddress((void**)&p_table,   g_table);
    cudaGetSymbolAddress((void**)&p_pf,      g_pf);
    cudaGetSymbolAddress((void**)&p_ps,      g_ps);
    cudaGetSymbolAddress((void**)&p_qkv,     g_qkv);
    cudaGetSymbolAddress((void**)&p_S,       g_S);
    cudaGetSymbolAddress((void**)&p_attn,    g_attn);
    cudaGetSymbolAddress((void**)&p_comb,    g_comb);
    cudaGetSymbolAddress((void**)&p_tpre,    g_tpre);
    cudaGetSymbolAddress((void**)&p_gatepre, g_gatepre);
    cudaGetSymbolAddress((void**)&p_qh,      g_qh);
    cudaGetSymbolAddress((void**)&p_sw,      g_sw);

    // normalized embedding rows for logits
    rownorm_kernel<<<VV, 256>>>(soma_w);

    // fast-GRU input-gate token table: [V,3D] = soma_w @ fast_wih^T + fast_bih
    gemm(soma_w, fast_wih, fast_bih, p_table, 256, 1536, 512, 512, 512, 1536,
         1.f, 1, 0, 0, 0, true, false);

    // fused pipelined GRUs -> p_f, comb[:,0:512], p_s, hf1, hs1
    static int smem_set = 0;
    if (!smem_set) {
        cudaFuncSetAttribute(fused_gru_kernel,
                             cudaFuncAttributeMaxDynamicSharedMemorySize, 36 * DD * 4);
        smem_set = 1;
    }
    fused_gru_kernel<<<FUSE_BLOCKS, 256, 36 * DD * 4>>>(
        fast_whh, fast_bhh, slow_wih, slow_bih, slow_whh, slow_bhh,
        p_table, x, h_f, h_s, p_pf, p_comb, p_ps, out_hf, out_hs);
    reset_bar_kernel<<<1, 1>>>();

    // projections from p_s
    gemm(p_ps, qkv_w,  qkv_b,  p_qkv,     1024, 1536, 512, 512, 512, 1536, 1.f, 1, 0, 0, 0, true, false);
    gemm(p_ps, gate_w, gate_b, p_gatepre, 1024,  512, 512, 512, 512,  512, 1.f, 1, 0, 0, 0, true, false);
    gemm(p_ps, hip_qw, hip_qb, p_qh,      1024,  512, 512, 512, 512,  512, 1.f, 1, 0, 0, 0, true, false);

    // q,k <- elu+1
    elu_qk_kernel<<<(BT * 1024) / 256, 256>>>();

    // linear attention == causal attention: S = q k^T (masked), per batch
    gemm(p_qkv, p_qkv + 512, nullptr, p_S, 512, 512, 512, 1536, 1536, 512,
         1.f, 2, 512LL * 1536, 512LL * 1536, 512LL * 512, true, true);
    den_kernel<<<BT, 256>>>();
    // num = S @ v -> combined[:, 1024:1536]
    gemm(p_S, p_qkv + 1024, nullptr, p_comb + 1024, 512, 512, 512, 512, 1536, 2048,
         1.f, 2, 512LL * 512, 512LL * 1536, 512LL * 2048, false, false);
    div_kernel<<<(BT * DD) / 256, 256>>>();

    // intent = tanh(LN(gatepre)) -> combined[:, 512:1024]
    ln_kernel<<<BT, 256>>>(p_gatepre, gate_g, gate_bb, p_comb + 512, 2048, 0);

    // hippocampus: attn = softmax(qh @ mem^T / sqrt(D)); episodes = attn @ mem
    gemm(p_qh, mem_bank, nullptr, p_attn, 1024, 256, 512, 512, 512, 256,
         0.044194173824159216f, 1, 0, 0, 0, true, false);
    softmax_kernel<<<BT, 256>>>();
    gemm(p_attn, mem_bank, nullptr, p_comb + 1536, 1024, 512, 256, 256, 512, 2048,
         1.f, 1, 0, 0, 0, false, false);

    // thought = LN(tanh(combined @ axon_w^T + axon_b))
    gemm(p_comb, axon_w, axon_b, p_tpre, 1024, 512, 2048, 2048, 2048, 512,
         1.f, 1, 0, 0, 0, true, false);
    ln_kernel<<<BT, 256>>>(p_tpre, norm_g, norm_b, out_thought, 512, 1);

    // logits = (thought @ sw^T) * 16
    gemm(out_thought, p_sw, nullptr, out_logits, 1024, 256, 512, 512, 512, 256,
         16.f, 1, 0, 0, 0, true, false);
}

// round 6
// speedup vs baseline: 1.3491x; 1.1144x over previous
#include <cuda_runtime.h>
#include <math.h>

#define TT 512
#define DD 512
#define NBATCH 2
#define VV 256
#define MMEM 256
#define BT 1024
#define D3 1536
#define FUSE_BLOCKS 128
#define UNITS 4
#define GRU_THREADS 384

// ---------------- static device scratch ----------------
__device__ float g_table[VV * D3];
__device__ float g_pf[BT * DD];
__device__ float g_ps[BT * DD];
__device__ float g_qkv[BT * D3];
__device__ float g_S[NBATCH * TT * TT];
__device__ float g_den[BT];
__device__ float g_attn[BT * MMEM];
__device__ float g_comb[BT * 2048];
__device__ float g_tpre[BT * DD];
__device__ float g_gatepre[BT * DD];
__device__ float g_qh[BT * DD];
__device__ float g_sw[VV * DD];
__device__ float g_hf3[3][NBATCH * DD];
__device__ float g_hs3[3][NBATCH * DD];
__device__ unsigned g_bar;

// ---------------- block reductions ----------------
__device__ __forceinline__ float block_red_sum(float v, float* sb) {
    __syncthreads();
    int lane = threadIdx.x & 31, w = threadIdx.x >> 5;
    #pragma unroll
    for (int o = 16; o; o >>= 1) v += __shfl_xor_sync(0xffffffffu, v, o);
    if (lane == 0) sb[w] = v;
    __syncthreads();
    float r = (lane < (int)(blockDim.x >> 5)) ? sb[lane] : 0.f;
    #pragma unroll
    for (int o = 16; o; o >>= 1) r += __shfl_xor_sync(0xffffffffu, r, o);
    return r;
}

__device__ __forceinline__ float block_red_max(float v, float* sb) {
    __syncthreads();
    int lane = threadIdx.x & 31, w = threadIdx.x >> 5;
    #pragma unroll
    for (int o = 16; o; o >>= 1) v = fmaxf(v, __shfl_xor_sync(0xffffffffu, v, o));
    if (lane == 0) sb[w] = v;
    __syncthreads();
    float r = (lane < (int)(blockDim.x >> 5)) ? sb[lane] : -3.4e38f;
    #pragma unroll
    for (int o = 16; o; o >>= 1) r = fmaxf(r, __shfl_xor_sync(0xffffffffu, r, o));
    return r;
}

// ---------------- global barrier: one arriver/block, per-warp spin ----------------
__device__ __forceinline__ void grid_bar(unsigned no) {
    __syncthreads();
    if (threadIdx.x == 0)
        asm volatile("red.release.gpu.global.add.u32 [%0], 1;" :: "l"(&g_bar) : "memory");
    if ((threadIdx.x & 31) == 0) {
        unsigned target = no * FUSE_BLOCKS;
        unsigned v;
        do {
            asm volatile("ld.acquire.gpu.u32 %0, [%1];" : "=r"(v) : "l"(&g_bar) : "memory");
        } while (v < target);
    }
    __syncwarp();
}

__global__ void reset_bar_kernel() { g_bar = 0u; }

__device__ __forceinline__ float sigf(float x) { return 1.f / (1.f + expf(-x)); }

#define FMA2(d, a, b, c) \
    asm("fma.rn.f32x2 %0, %1, %2, %3;" : "=l"(d) : "l"(a), "l"(b), "l"(c))

// ---------------- fused pipelined GRU v3 ----------------
// 128 blocks x 384 threads. Warp = (trio, unit): trio 0 = fast_whh dots,
// trio 1 = slow_wih dots, trio 2 = slow_whh dots; each covers both batches.
// Weights live entirely in registers (48 floats/lane), loaded once.
__global__ void __launch_bounds__(GRU_THREADS) fused_gru_kernel(
    const float* __restrict__ fast_whh, const float* __restrict__ fast_bhh,
    const float* __restrict__ slow_wih, const float* __restrict__ slow_bih,
    const float* __restrict__ slow_whh, const float* __restrict__ slow_bhh,
    const float* __restrict__ gi_table, const int* __restrict__ toks,
    const float* __restrict__ hf0, const float* __restrict__ hs0,
    float* __restrict__ pf, float* __restrict__ comb, float* __restrict__ ps,
    float* __restrict__ hfT, float* __restrict__ hsT)
{
    __shared__ float sg[3][3][NBATCH][UNITS];   // [trio][gate][batch][unit]
    const int tid = threadIdx.x;
    const int w = tid >> 5, lane = tid & 31;
    const int il = w & 3, tr = w >> 2;          // unit-in-block, trio
    const int ibase = blockIdx.x * UNITS;
    const int i = ibase + il;

    // ---- load this lane's weight slice into registers (3 rows x 16 cols) ----
    const float* Wsrc = (tr == 0) ? fast_whh : ((tr == 1) ? slow_wih : slow_whh);
    ulonglong2 wreg[3][4];
    #pragma unroll
    for (int g = 0; g < 3; g++)
        #pragma unroll
        for (int j = 0; j < 4; j++)
            wreg[g][j] = *(const ulonglong2*)&Wsrc[(size_t)(g * DD + i) * DD + lane * 4 + j * 128];

    // ---- cell-thread setup: warp0 lanes 0-7 = fast cells, warp1 lanes 0-7 = slow cells ----
    const int cb = lane >> 2, cil = lane & 3;   // cell batch, cell unit
    const int ci = ibase + cil;
    float fb_r = 0.f, fb_z = 0.f, fb_n = 0.f;
    float sbi_r = 0.f, sbi_z = 0.f, sbi_n = 0.f, sbh_r = 0.f, sbh_z = 0.f, sbh_n = 0.f;
    if (w == 0 && lane < 8) {
        fb_r = fast_bhh[ci]; fb_z = fast_bhh[DD + ci]; fb_n = fast_bhh[2 * DD + ci];
        g_hf3[0][cb * DD + ci] = hf0[cb * DD + ci];
    }
    if (w == 1 && lane < 8) {
        sbi_r = slow_bih[ci]; sbi_z = slow_bih[DD + ci]; sbi_n = slow_bih[2 * DD + ci];
        sbh_r = slow_bhh[ci]; sbh_z = slow_bhh[DD + ci]; sbh_n = slow_bhh[2 * DD + ci];
        g_hs3[0][cb * DD + ci] = hs0[cb * DD + ci];
    }
    grid_bar(1u);

    for (int t = 0; t <= TT; t++) {
        const int cur = t % 3, nxt = (t + 1) % 3;
        const int cur_s = (t + 2) % 3, nxt_s = t % 3;

        // cell-thread prefetches (L2 latency hidden under the dot compute)
        float gr = 0.f, gz = 0.f, gn = 0.f, hprev = 0.f;
        if (w == 0 && lane < 8 && t < TT) {
            const int row = cb * TT + t;
            const float* gi = gi_table + (size_t)__ldg(&toks[row]) * D3;
            gr = __ldg(gi + ci); gz = __ldg(gi + DD + ci); gn = __ldg(gi + 2 * DD + ci);
            hprev = __ldcg(&g_hf3[cur][cb * DD + ci]);
        }
        if (w == 1 && lane < 8 && t >= 1)
            hprev = __ldcg(&g_hs3[cur_s][cb * DD + ci]);

        // ---- load this trio's input vectors (both batches) ----
        ulonglong2 xv[NBATCH][4];
        if (tr == 0) {
            #pragma unroll
            for (int b = 0; b < NBATCH; b++)
                #pragma unroll
                for (int j = 0; j < 4; j++)
                    xv[b][j] = __ldcg((const ulonglong2*)&g_hf3[cur][b * DD + lane * 4 + j * 128]);
        } else if (tr == 1) {
            const int tm1 = (t > 0) ? t - 1 : 0;
            #pragma unroll
            for (int b = 0; b < NBATCH; b++) {
                const float* pfb = pf + (size_t)(b * TT + tm1) * DD;
                #pragma unroll
                for (int j = 0; j < 4; j++)
                    xv[b][j] = __ldcg((const ulonglong2*)(pfb + lane * 4 + j * 128));
            }
        } else {
            #pragma unroll
            for (int b = 0; b < NBATCH; b++)
                #pragma unroll
                for (int j = 0; j < 4; j++)
                    xv[b][j] = __ldcg((const ulonglong2*)&g_hs3[cur_s][b * DD + lane * 4 + j * 128]);
        }

        // ---- 6 dot products via packed f32x2 FFMA ----
        unsigned long long acc2[3][NBATCH];
        #pragma unroll
        for (int g = 0; g < 3; g++)
            #pragma unroll
            for (int b = 0; b < NBATCH; b++) acc2[g][b] = 0ull;
        #pragma unroll
        for (int j = 0; j < 4; j++)
            #pragma unroll
            for (int g = 0; g < 3; g++)
                #pragma unroll
                for (int b = 0; b < NBATCH; b++) {
                    FMA2(acc2[g][b], wreg[g][j].x, xv[b][j].x, acc2[g][b]);
                    FMA2(acc2[g][b], wreg[g][j].y, xv[b][j].y, acc2[g][b]);
                }

        float a[3][NBATCH];
        #pragma unroll
        for (int g = 0; g < 3; g++)
            #pragma unroll
            for (int b = 0; b < NBATCH; b++) {
                float lo, hi;
                asm("mov.b64 {%0, %1}, %2;" : "=f"(lo), "=f"(hi) : "l"(acc2[g][b]));
                a[g][b] = lo + hi;
            }
        #pragma unroll
        for (int o = 16; o; o >>= 1)
            #pragma unroll
            for (int g = 0; g < 3; g++)
                #pragma unroll
                for (int b = 0; b < NBATCH; b++)
                    a[g][b] += __shfl_xor_sync(0xffffffffu, a[g][b], o);

        if (lane == 0) {
            #pragma unroll
            for (int g = 0; g < 3; g++)
                #pragma unroll
                for (int b = 0; b < NBATCH; b++)
                    sg[tr][g][b][il] = a[g][b];
        }
        __syncthreads();

        // ---- cell updates ----
        if (w == 0 && lane < 8 && t < TT) {         // fast GRU step t
            const int row = cb * TT + t;
            float r = sigf(gr + sg[0][0][cb][cil] + fb_r);
            float z = sigf(gz + sg[0][1][cb][cil] + fb_z);
            float n = tanhf(gn + r * (sg[0][2][cb][cil] + fb_n));
            float hnew = (1.f - z) * n + z * hprev;
            g_hf3[nxt][cb * DD + ci] = hnew;
            pf[(size_t)row * DD + ci] = hnew;
            comb[(size_t)row * 2048 + ci] = hnew;
            if (t == TT - 1) hfT[cb * DD + ci] = hnew;
        }
        if (w == 1 && lane < 8 && t >= 1) {         // slow GRU step t-1
            const int ts = t - 1, row = cb * TT + ts;
            float r = sigf(sg[1][0][cb][cil] + sbi_r + sg[2][0][cb][cil] + sbh_r);
            float z = sigf(sg[1][1][cb][cil] + sbi_z + sg[2][1][cb][cil] + sbh_z);
            float n = tanhf(sg[1][2][cb][cil] + sbi_n + r * (sg[2][2][cb][cil] + sbh_n));
            float hnew = (1.f - z) * n + z * hprev;
            g_hs3[nxt_s][cb * DD + ci] = hnew;
            ps[(size_t)row * DD + ci] = hnew;
            if (ts == TT - 1) hsT[cb * DD + ci] = hnew;
        }
        grid_bar((unsigned)(t + 2));
    }
}

// ---------------- double-buffered tiled GEMM ----------------
// TB=true : Bm stored [N,K]  (C = A @ Bm^T);  TB=false: Bm stored [K,N]
template <bool TB, bool CAUSAL>
__global__ void __launch_bounds__(256) gemm_kernel(
    const float* __restrict__ A, const float* __restrict__ Bm,
    const float* __restrict__ bias, float* __restrict__ C,
    int M, int N, int K, int lda, int ldb, int ldc,
    long long sA, long long sB, long long sC, float scale)
{
    __shared__ __align__(16) float As[2][16][68];
    __shared__ __align__(16) float Bs[2][16][68];
    const int z = blockIdx.z;
    A += (size_t)z * sA; Bm += (size_t)z * sB; C += (size_t)z * sC;
    const int m0 = blockIdx.y * 64, n0 = blockIdx.x * 64;
    const int tid = threadIdx.x;
    const int lr = tid >> 2, lc = (tid & 3) << 2;
    const int br = tid >> 4, bc = (tid & 15) << 2;
    const int ty = tid >> 4, tx = tid & 15;

    float4 av = *(const float4*)(A + (size_t)(m0 + lr) * lda + lc);
    float4 bv;
    if (TB) bv = *(const float4*)(Bm + (size_t)(n0 + lr) * ldb + lc);
    else    bv = *(const float4*)(Bm + (size_t)br * ldb + n0 + bc);

    As[0][lc + 0][lr] = av.x; As[0][lc + 1][lr] = av.y;
    As[0][lc + 2][lr] = av.z; As[0][lc + 3][lr] = av.w;
    if (TB) {
        Bs[0][lc + 0][lr] = bv.x; Bs[0][lc + 1][lr] = bv.y;
        Bs[0][lc + 2][lr] = bv.z; Bs[0][lc + 3][lr] = bv.w;
    } else {
        *(float4*)&Bs[0][br][bc] = bv;
    }
    __syncthreads();

    float acc[4][4] = {};
    const int P = K >> 4;
    int buf = 0;
    for (int p = 0; p < P; p++) {
        if (p + 1 < P) {
            const int k0n = (p + 1) << 4;
            av = *(const float4*)(A + (size_t)(m0 + lr) * lda + k0n + lc);
            if (TB) bv = *(const float4*)(Bm + (size_t)(n0 + lr) * ldb + k0n + lc);
            else    bv = *(const float4*)(Bm + (size_t)(k0n + br) * ldb + n0 + bc);
        }
        #pragma unroll
        for (int k = 0; k < 16; k++) {
            float4 a  = *(const float4*)&As[buf][k][ty << 2];
            float4 b4 = *(const float4*)&Bs[buf][k][tx << 2];
            float af[4] = {a.x, a.y, a.z, a.w};
            float bf[4] = {b4.x, b4.y, b4.z, b4.w};
            #pragma unroll
            for (int ii = 0; ii < 4; ii++)
                #pragma unroll
                for (int jj = 0; jj < 4; jj++)
                    acc[ii][jj] = fmaf(af[ii], bf[jj], acc[ii][jj]);
        }
        if (p + 1 < P) {
            const int nb = buf ^ 1;
            As[nb][lc + 0][lr] = av.x; As[nb][lc + 1][lr] = av.y;
            As[nb][lc + 2][lr] = av.z; As[nb][lc + 3][lr] = av.w;
            if (TB) {
                Bs[nb][lc + 0][lr] = bv.x; Bs[nb][lc + 1][lr] = bv.y;
                Bs[nb][lc + 2][lr] = bv.z; Bs[nb][lc + 3][lr] = bv.w;
            } else {
                *(float4*)&Bs[nb][br][bc] = bv;
            }
            __syncthreads();
            buf = nb;
        }
    }

    const int mm = m0 + (ty << 2), nn = n0 + (tx << 2);
    #pragma unroll
    for (int ii = 0; ii < 4; ii++) {
        #pragma unroll
        for (int jj = 0; jj < 4; jj++) {
            float c = acc[ii][jj] * scale;
            if (bias) c += bias[nn + jj];
            if (CAUSAL && (nn + jj) > (mm + ii)) c = 0.f;
            C[(size_t)(mm + ii) * ldc + nn + jj] = c;
        }
    }
}

// ---------------- small kernels ----------------
__global__ void elu_qk_kernel() {
    int idx = blockIdx.x * blockDim.x + threadIdx.x;
    if (idx >= BT * 1024) return;
    int row = idx >> 10, c = idx & 1023;
    float* p = &g_qkv[(size_t)row * D3 + c];
    float x = *p;
    *p = x > 0.f ? x + 1.f : expf(x);
}

__global__ void den_kernel() {
    __shared__ float sb[32];
    int row = blockIdx.x;
    float s = 0.f;
    for (int c = threadIdx.x; c < TT; c += 256) s += g_S[(size_t)row * TT + c];
    s = block_red_sum(s, sb);
    if (threadIdx.x == 0) g_den[row] = s;
}

__global__ void div_kernel() {
    int idx = blockIdx.x * blockDim.x + threadIdx.x;
    if (idx >= BT * DD) return;
    int row = idx >> 9, j = idx & 511;
    g_comb[(size_t)row * 2048 + 1024 + j] /= (g_den[row] + 1e-6f);
}

__global__ void softmax_kernel() {
    __shared__ float sb[32];
    int row = blockIdx.x;
    float x = g_attn[(size_t)row * MMEM + threadIdx.x];
    float m = block_red_max(x, sb);
    float e = expf(x - m);
    float s = block_red_sum(e, sb);
    g_attn[(size_t)row * MMEM + threadIdx.x] = e / s;
}

// mode 0: out = tanh(LN(in));  mode 1: out = LN(tanh(in))
__global__ void ln_kernel(const float* __restrict__ in, const float* __restrict__ gg,
                          const float* __restrict__ bb, float* __restrict__ out,
                          int ldo, int mode)
{
    __shared__ float sb[32];
    int row = blockIdx.x, tid = threadIdx.x;
    float x0 = in[(size_t)row * DD + tid];
    float x1 = in[(size_t)row * DD + 256 + tid];
    if (mode == 1) { x0 = tanhf(x0); x1 = tanhf(x1); }
    float s  = block_red_sum(x0 + x1, sb);
    float sq = block_red_sum(x0 * x0 + x1 * x1, sb);
    float mean = s * (1.f / 512.f);
    float var  = sq * (1.f / 512.f) - mean * mean;
    float rstd = rsqrtf(var + 1e-5f);
    float y0 = (x0 - mean) * rstd * gg[tid] + bb[tid];
    float y1 = (x1 - mean) * rstd * gg[256 + tid] + bb[256 + tid];
    if (mode == 0) { y0 = tanhf(y0); y1 = tanhf(y1); }
    out[(size_t)row * ldo + tid] = y0;
    out[(size_t)row * ldo + 256 + tid] = y1;
}

__global__ void rownorm_kernel(const float* __restrict__ src) {
    __shared__ float sb[32];
    int row = blockIdx.x, tid = threadIdx.x;
    float x0 = src[(size_t)row * DD + tid];
    float x1 = src[(size_t)row * DD + 256 + tid];
    float ss = block_red_sum(x0 * x0 + x1 * x1, sb);
    float inv = 1.f / fmaxf(sqrtf(ss), 1e-12f);
    g_sw[(size_t)row * DD + tid] = x0 * inv;
    g_sw[(size_t)row * DD + 256 + tid] = x1 * inv;
}

// ---------------- host ----------------
static inline void gemm(const float* A, const float* B, const float* bias, float* C,
                        int M, int N, int K, int lda, int ldb, int ldc,
                        float scale, int batch, long long sA, long long sB, long long sC,
                        bool tb, bool causal)
{
    dim3 grid(N / 64, M / 64, batch);
    if (tb) {
        if (causal)
            gemm_kernel<true, true><<<grid, 256>>>(A, B, bias, C, M, N, K, lda, ldb, ldc, sA, sB, sC, scale);
        else
            gemm_kernel<true, false><<<grid, 256>>>(A, B, bias, C, M, N, K, lda, ldb, ldc, sA, sB, sC, scale);
    } else {
        gemm_kernel<false, false><<<grid, 256>>>(A, B, bias, C, M, N, K, lda, ldb, ldc, sA, sB, sC, scale);
    }
}

extern "C" void kernel_launch(void* const* d_in, const int* in_sizes, int n_in,
                              void* d_out, int out_size)
{
    (void)in_sizes; (void)n_in; (void)out_size;
    const int*   x        = (const int*)d_in[0];
    const float* h_f      = (const float*)d_in[1];
    const float* h_s      = (const float*)d_in[2];
    const float* soma_w   = (const float*)d_in[3];
    const float* fast_wih = (const float*)d_in[4];
    const float* fast_whh = (const float*)d_in[5];
    const float* fast_bih = (const float*)d_in[6];
    const float* fast_bhh = (const float*)d_in[7];
    const float* slow_wih = (const float*)d_in[8];
    const float* slow_whh = (const float*)d_in[9];
    const float* slow_bih = (const float*)d_in[10];
    const float* slow_bhh = (const float*)d_in[11];
    const float* qkv_w    = (const float*)d_in[12];
    const float* qkv_b    = (const float*)d_in[13];
    const float* gate_w   = (const float*)d_in[14];
    const float* gate_b   = (const float*)d_in[15];
    const float* gate_g   = (const float*)d_in[16];
    const float* gate_bb  = (const float*)d_in[17];
    const float* mem_bank = (const float*)d_in[18];
    const float* hip_qw   = (const float*)d_in[19];
    const float* hip_qb   = (const float*)d_in[20];
    const float* axon_w   = (const float*)d_in[21];
    const float* axon_b   = (const float*)d_in[22];
    const float* norm_g   = (const float*)d_in[23];
    const float* norm_b   = (const float*)d_in[24];

    float* out = (float*)d_out;
    float* out_logits  = out;            // [B,T,V]
    float* out_thought = out + 262144;   // [B,T,D]
    float* out_hf      = out + 786432;   // [1,B,D]
    float* out_hs      = out + 787456;   // [1,B,D]

    float *p_table, *p_pf, *p_ps, *p_qkv, *p_S, *p_attn, *p_comb,
          *p_tpre, *p_gatepre, *p_qh, *p_sw;
    cudaGetSymbolAddress((void**)&p_table,   g_table);
    cudaGetSymbolAddress((void**)&p_pf,      g_pf);
    cudaGetSymbolAddress((void**)&p_ps,      g_ps);
    cudaGetSymbolAddress((void**)&p_qkv,     g_qkv);
    cudaGetSymbolAddress((void**)&p_S,       g_S);
    cudaGetSymbolAddress((void**)&p_attn,    g_attn);
    cudaGetSymbolAddress((void**)&p_comb,    g_comb);
    cudaGetSymbolAddress((void**)&p_tpre,    g_tpre);
    cudaGetSymbolAddress((void**)&p_gatepre, g_gatepre);
    cudaGetSymbolAddress((void**)&p_qh,      g_qh);
    cudaGetSymbolAddress((void**)&p_sw,      g_sw);

    // normalized embedding rows for logits
    rownorm_kernel<<<VV, 256>>>(soma_w);

    // fast-GRU input-gate token table: [V,3D] = soma_w @ fast_wih^T + fast_bih
    gemm(soma_w, fast_wih, fast_bih, p_table, 256, 1536, 512, 512, 512, 1536,
         1.f, 1, 0, 0, 0, true, false);

    // reset barrier BEFORE the GRU (identical semantics; puts fused_gru in the
    // ncu -s 5 -c 1 window so the next round gets a real profile)
    reset_bar_kernel<<<1, 1>>>();

    // fused pipelined GRUs -> p_f, comb[:,0:512], p_s, hf1, hs1
    fused_gru_kernel<<<FUSE_BLOCKS, GRU_THREADS>>>(
        fast_whh, fast_bhh, slow_wih, slow_bih, slow_whh, slow_bhh,
        p_table, x, h_f, h_s, p_pf, p_comb, p_ps, out_hf, out_hs);

    // projections from p_s
    gemm(p_ps, qkv_w,  qkv_b,  p_qkv,     1024, 1536, 512, 512, 512, 1536, 1.f, 1, 0, 0, 0, true, false);
    gemm(p_ps, gate_w, gate_b, p_gatepre, 1024,  512, 512, 512, 512,  512, 1.f, 1, 0, 0, 0, true, false);
    gemm(p_ps, hip_qw, hip_qb, p_qh,      1024,  512, 512, 512, 512,  512, 1.f, 1, 0, 0, 0, true, false);

    // q,k <- elu+1
    elu_qk_kernel<<<(BT * 1024) / 256, 256>>>();

    // linear attention == causal attention: S = q k^T (masked), per batch
    gemm(p_qkv, p_qkv + 512, nullptr, p_S, 512, 512, 512, 1536, 1536, 512,
         1.f, 2, 512LL * 1536, 512LL * 1536, 512LL * 512, true, true);
    den_kernel<<<BT, 256>>>();
    // num = S @ v -> combined[:, 1024:1536]
    gemm(p_S, p_qkv + 1024, nullptr, p_comb + 1024, 512, 512, 512, 512, 1536, 2048,
         1.f, 2, 512LL * 512, 512LL * 1536, 512LL * 2048, false, false);
    div_kernel<<<(BT * DD) / 256, 256>>>();

    // intent = tanh(LN(gatepre)) -> combined[:, 512:1024]
    ln_kernel<<<BT, 256>>>(p_gatepre, gate_g, gate_bb, p_comb + 512, 2048, 0);

    // hippocampus: attn = softmax(qh @ mem^T / sqrt(D)); episodes = attn @ mem
    gemm(p_qh, mem_bank, nullptr, p_attn, 1024, 256, 512, 512, 512, 256,
         0.044194173824159216f, 1, 0, 0, 0, true, false);
    softmax_kernel<<<BT, 256>>>();
    gemm(p_attn, mem_bank, nullptr, p_comb + 1536, 1024, 512, 256, 256, 512, 2048,
         1.f, 1, 0, 0, 0, false, false);

    // thought = LN(tanh(combined @ axon_w^T + axon_b))
    gemm(p_comb, axon_w, axon_b, p_tpre, 1024, 512, 2048, 2048, 2048, 512,
         1.f, 1, 0, 0, 0, true, false);
    ln_kernel<<<BT, 256>>>(p_tpre, norm_g, norm_b, out_thought, 512, 1);

    // logits = (thought @ sw^T) * 16
    gemm(out_thought, p_sw, nullptr, out_logits, 1024, 256, 512, 512, 512, 256,
         16.f, 1, 0, 0, 0, true, false);
}

// round 7
// speedup vs baseline: 1.7601x; 1.3046x over previous
#include <cuda_runtime.h>
#include <math.h>

#define TT 512
#define DD 512
#define NBATCH 2
#define VV 256
#define MMEM 256
#define BT 1024
#define D3 1536
#define FUSE_BLOCKS 128
#define UNITS 4
#define GRU_THREADS 384

// ---------------- static device scratch ----------------
__device__ float g_table[VV * D3];
__device__ float g_pf[BT * DD];
__device__ float g_ps[BT * DD];
__device__ float g_qkv[BT * D3];
__device__ float g_S[NBATCH * TT * TT];
__device__ float g_den[BT];
__device__ float g_attn[BT * MMEM];
__device__ float g_comb[BT * 2048];
__device__ float g_tpre[BT * DD];
__device__ float g_gatepre[BT * DD];
__device__ float g_qh[BT * DD];
__device__ float g_sw[VV * DD];
__device__ float g_hf3[3][NBATCH * DD];
__device__ float g_hs3[3][NBATCH * DD];
__device__ unsigned g_bar;

// ---------------- block reductions ----------------
__device__ __forceinline__ float block_red_sum(float v, float* sb) {
    __syncthreads();
    int lane = threadIdx.x & 31, w = threadIdx.x >> 5;
    #pragma unroll
    for (int o = 16; o; o >>= 1) v += __shfl_xor_sync(0xffffffffu, v, o);
    if (lane == 0) sb[w] = v;
    __syncthreads();
    float r = (lane < (int)(blockDim.x >> 5)) ? sb[lane] : 0.f;
    #pragma unroll
    for (int o = 16; o; o >>= 1) r += __shfl_xor_sync(0xffffffffu, r, o);
    return r;
}

__device__ __forceinline__ float block_red_max(float v, float* sb) {
    __syncthreads();
    int lane = threadIdx.x & 31, w = threadIdx.x >> 5;
    #pragma unroll
    for (int o = 16; o; o >>= 1) v = fmaxf(v, __shfl_xor_sync(0xffffffffu, v, o));
    if (lane == 0) sb[w] = v;
    __syncthreads();
    float r = (lane < (int)(blockDim.x >> 5)) ? sb[lane] : -3.4e38f;
    #pragma unroll
    for (int o = 16; o; o >>= 1) r = fmaxf(r, __shfl_xor_sync(0xffffffffu, r, o));
    return r;
}

// ---------------- global barrier: single poller per block ----------------
__device__ __forceinline__ void grid_bar(unsigned no) {
    __syncthreads();
    if (threadIdx.x == 0) {
        asm volatile("red.release.gpu.global.add.u32 [%0], 1;" :: "l"(&g_bar) : "memory");
        unsigned target = no * FUSE_BLOCKS;
        unsigned v;
        do {
            asm volatile("ld.acquire.gpu.u32 %0, [%1];" : "=r"(v) : "l"(&g_bar) : "memory");
        } while (v < target);
    }
    __syncthreads();
}

__global__ void reset_bar_kernel() { g_bar = 0u; }

__device__ __forceinline__ float sigf(float x) { return 1.f / (1.f + expf(-x)); }

#define FMA2(d, a, b, c) \
    asm("fma.rn.f32x2 %0, %1, %2, %3;" : "=l"(d) : "l"(a), "l"(b), "l"(c))

// ---------------- fused pipelined GRU ----------------
// 128 blocks x 384 threads. Warp = (trio, unit): trio 0 = fast_whh dots,
// trio 1 = slow_wih dots, trio 2 = slow_whh dots; weights in registers.
__global__ void __launch_bounds__(GRU_THREADS) fused_gru_kernel(
    const float* __restrict__ fast_whh, const float* __restrict__ fast_bhh,
    const float* __restrict__ slow_wih, const float* __restrict__ slow_bih,
    const float* __restrict__ slow_whh, const float* __restrict__ slow_bhh,
    const float* __restrict__ gi_table, const int* __restrict__ toks,
    const float* __restrict__ hf0, const float* __restrict__ hs0,
    float* __restrict__ pf, float* __restrict__ comb, float* __restrict__ ps,
    float* __restrict__ hfT, float* __restrict__ hsT)
{
    __shared__ float sg[3][3][NBATCH][UNITS];   // [trio][gate][batch][unit]
    const int tid = threadIdx.x;
    const int w = tid >> 5, lane = tid & 31;
    const int il = w & 3, tr = w >> 2;
    const int ibase = blockIdx.x * UNITS;
    const int i = ibase + il;

    const float* Wsrc = (tr == 0) ? fast_whh : ((tr == 1) ? slow_wih : slow_whh);
    ulonglong2 wreg[3][4];
    #pragma unroll
    for (int g = 0; g < 3; g++)
        #pragma unroll
        for (int j = 0; j < 4; j++)
            wreg[g][j] = *(const ulonglong2*)&Wsrc[(size_t)(g * DD + i) * DD + lane * 4 + j * 128];

    const int cb = lane >> 2, cil = lane & 3;
    const int ci = ibase + cil;
    float fb_r = 0.f, fb_z = 0.f, fb_n = 0.f;
    float sbi_r = 0.f, sbi_z = 0.f, sbi_n = 0.f, sbh_r = 0.f, sbh_z = 0.f, sbh_n = 0.f;
    if (w == 0 && lane < 8) {
        fb_r = fast_bhh[ci]; fb_z = fast_bhh[DD + ci]; fb_n = fast_bhh[2 * DD + ci];
        g_hf3[0][cb * DD + ci] = hf0[cb * DD + ci];
    }
    if (w == 1 && lane < 8) {
        sbi_r = slow_bih[ci]; sbi_z = slow_bih[DD + ci]; sbi_n = slow_bih[2 * DD + ci];
        sbh_r = slow_bhh[ci]; sbh_z = slow_bhh[DD + ci]; sbh_n = slow_bhh[2 * DD + ci];
        g_hs3[0][cb * DD + ci] = hs0[cb * DD + ci];
    }
    grid_bar(1u);

    for (int t = 0; t <= TT; t++) {
        const int cur = t % 3, nxt = (t + 1) % 3;
        const int cur_s = (t + 2) % 3, nxt_s = t % 3;

        float gr = 0.f, gz = 0.f, gn = 0.f, hprev = 0.f;
        if (w == 0 && lane < 8 && t < TT) {
            const int row = cb * TT + t;
            const float* gi = gi_table + (size_t)__ldg(&toks[row]) * D3;
            gr = __ldg(gi + ci); gz = __ldg(gi + DD + ci); gn = __ldg(gi + 2 * DD + ci);
            hprev = __ldcg(&g_hf3[cur][cb * DD + ci]);
        }
        if (w == 1 && lane < 8 && t >= 1)
            hprev = __ldcg(&g_hs3[cur_s][cb * DD + ci]);

        ulonglong2 xv[NBATCH][4];
        if (tr == 0) {
            #pragma unroll
            for (int b = 0; b < NBATCH; b++)
                #pragma unroll
                for (int j = 0; j < 4; j++)
                    xv[b][j] = __ldcg((const ulonglong2*)&g_hf3[cur][b * DD + lane * 4 + j * 128]);
        } else if (tr == 1) {
            const int tm1 = (t > 0) ? t - 1 : 0;
            #pragma unroll
            for (int b = 0; b < NBATCH; b++) {
                const float* pfb = pf + (size_t)(b * TT + tm1) * DD;
                #pragma unroll
                for (int j = 0; j < 4; j++)
                    xv[b][j] = __ldcg((const ulonglong2*)(pfb + lane * 4 + j * 128));
            }
        } else {
            #pragma unroll
            for (int b = 0; b < NBATCH; b++)
                #pragma unroll
                for (int j = 0; j < 4; j++)
                    xv[b][j] = __ldcg((const ulonglong2*)&g_hs3[cur_s][b * DD + lane * 4 + j * 128]);
        }

        unsigned long long acc2[3][NBATCH];
        #pragma unroll
        for (int g = 0; g < 3; g++)
            #pragma unroll
            for (int b = 0; b < NBATCH; b++) acc2[g][b] = 0ull;
        #pragma unroll
        for (int j = 0; j < 4; j++)
            #pragma unroll
            for (int g = 0; g < 3; g++)
                #pragma unroll
                for (int b = 0; b < NBATCH; b++) {
                    FMA2(acc2[g][b], wreg[g][j].x, xv[b][j].x, acc2[g][b]);
                    FMA2(acc2[g][b], wreg[g][j].y, xv[b][j].y, acc2[g][b]);
                }

        float a[3][NBATCH];
        #pragma unroll
        for (int g = 0; g < 3; g++)
            #pragma unroll
            for (int b = 0; b < NBATCH; b++) {
                float lo, hi;
                asm("mov.b64 {%0, %1}, %2;" : "=f"(lo), "=f"(hi) : "l"(acc2[g][b]));
                a[g][b] = lo + hi;
            }
        #pragma unroll
        for (int o = 16; o; o >>= 1)
            #pragma unroll
            for (int g = 0; g < 3; g++)
                #pragma unroll
                for (int b = 0; b < NBATCH; b++)
                    a[g][b] += __shfl_xor_sync(0xffffffffu, a[g][b], o);

        if (lane == 0) {
            #pragma unroll
            for (int g = 0; g < 3; g++)
                #pragma unroll
                for (int b = 0; b < NBATCH; b++)
                    sg[tr][g][b][il] = a[g][b];
        }
        __syncthreads();

        if (w == 0 && lane < 8 && t < TT) {         // fast GRU step t
            const int row = cb * TT + t;
            float r = sigf(gr + sg[0][0][cb][cil] + fb_r);
            float z = sigf(gz + sg[0][1][cb][cil] + fb_z);
            float n = tanhf(gn + r * (sg[0][2][cb][cil] + fb_n));
            float hnew = (1.f - z) * n + z * hprev;
            g_hf3[nxt][cb * DD + ci] = hnew;
            pf[(size_t)row * DD + ci] = hnew;
            comb[(size_t)row * 2048 + ci] = hnew;
            if (t == TT - 1) hfT[cb * DD + ci] = hnew;
        }
        if (w == 1 && lane < 8 && t >= 1) {         // slow GRU step t-1
            const int ts = t - 1, row = cb * TT + ts;
            float r = sigf(sg[1][0][cb][cil] + sbi_r + sg[2][0][cb][cil] + sbh_r);
            float z = sigf(sg[1][1][cb][cil] + sbi_z + sg[2][1][cb][cil] + sbh_z);
            float n = tanhf(sg[1][2][cb][cil] + sbi_n + r * (sg[2][2][cb][cil] + sbh_n));
            float hnew = (1.f - z) * n + z * hprev;
            g_hs3[nxt_s][cb * DD + ci] = hnew;
            ps[(size_t)row * DD + ci] = hnew;
            if (ts == TT - 1) hsT[cb * DD + ci] = hnew;
        }
        if (t < TT) grid_bar((unsigned)(t + 2));   // no barrier needed after last step
    }
}

// ---------------- GEMM: 128x64 tile, 256 thr, 8x4/thread, f32x2 FMA ----------------
// TB=true : Bm stored [N,K]  (C = A @ Bm^T);  TB=false: Bm stored [K,N]
template <bool TB, bool CAUSAL>
__global__ void __launch_bounds__(256) gemm_kernel(
    const float* __restrict__ A, const float* __restrict__ Bm,
    const float* __restrict__ bias, float* __restrict__ C,
    int M, int N, int K, int lda, int ldb, int ldc,
    long long sA, long long sB, long long sC, float scale)
{
    __shared__ __align__(16) float As[2][16][132];
    __shared__ __align__(16) float Bs[2][16][68];
    const int z = blockIdx.z;
    A += (size_t)z * sA; Bm += (size_t)z * sB; C += (size_t)z * sC;
    const int m0 = blockIdx.y * 128, n0 = blockIdx.x * 64;
    const int tid = threadIdx.x;
    const int ar = tid >> 2, ac = (tid & 3) << 2;   // A (and TB-B) load map
    const int bk = tid >> 4, bn = (tid & 15) << 2;  // NN-B load map
    const int ty = tid >> 4, tx = tid & 15;

    float4 a0 = *(const float4*)(A + (size_t)(m0 + ar) * lda + ac);
    float4 a1 = *(const float4*)(A + (size_t)(m0 + ar + 64) * lda + ac);
    float4 bv;
    if (TB) bv = *(const float4*)(Bm + (size_t)(n0 + ar) * ldb + ac);
    else    bv = *(const float4*)(Bm + (size_t)bk * ldb + n0 + bn);

    {
        As[0][ac + 0][ar] = a0.x; As[0][ac + 1][ar] = a0.y;
        As[0][ac + 2][ar] = a0.z; As[0][ac + 3][ar] = a0.w;
        As[0][ac + 0][ar + 64] = a1.x; As[0][ac + 1][ar + 64] = a1.y;
        As[0][ac + 2][ar + 64] = a1.z; As[0][ac + 3][ar + 64] = a1.w;
        if (TB) {
            Bs[0][ac + 0][ar] = bv.x; Bs[0][ac + 1][ar] = bv.y;
            Bs[0][ac + 2][ar] = bv.z; Bs[0][ac + 3][ar] = bv.w;
        } else {
            *(float4*)&Bs[0][bk][bn] = bv;
        }
    }
    __syncthreads();

    unsigned long long acc[4][4];   // [row-pair][col]
    #pragma unroll
    for (int p2 = 0; p2 < 4; p2++)
        #pragma unroll
        for (int jj = 0; jj < 4; jj++) acc[p2][jj] = 0ull;

    const int P = K >> 4;
    int buf = 0;
    for (int p = 0; p < P; p++) {
        if (p + 1 < P) {
            const int k0n = (p + 1) << 4;
            a0 = *(const float4*)(A + (size_t)(m0 + ar) * lda + k0n + ac);
            a1 = *(const float4*)(A + (size_t)(m0 + ar + 64) * lda + k0n + ac);
            if (TB) bv = *(const float4*)(Bm + (size_t)(n0 + ar) * ldb + k0n + ac);
            else    bv = *(const float4*)(Bm + (size_t)(k0n + bk) * ldb + n0 + bn);
        }
        #pragma unroll
        for (int k = 0; k < 16; k++) {
            ulonglong2 alo = *(const ulonglong2*)&As[buf][k][ty << 3];
            ulonglong2 ahi = *(const ulonglong2*)&As[buf][k][(ty << 3) + 4];
            float4 b4 = *(const float4*)&Bs[buf][k][tx << 2];
            unsigned long long bd[4];
            asm("mov.b64 %0, {%1, %1};" : "=l"(bd[0]) : "f"(b4.x));
            asm("mov.b64 %0, {%1, %1};" : "=l"(bd[1]) : "f"(b4.y));
            asm("mov.b64 %0, {%1, %1};" : "=l"(bd[2]) : "f"(b4.z));
            asm("mov.b64 %0, {%1, %1};" : "=l"(bd[3]) : "f"(b4.w));
            #pragma unroll
            for (int jj = 0; jj < 4; jj++) {
                FMA2(acc[0][jj], alo.x, bd[jj], acc[0][jj]);
                FMA2(acc[1][jj], alo.y, bd[jj], acc[1][jj]);
                FMA2(acc[2][jj], ahi.x, bd[jj], acc[2][jj]);
                FMA2(acc[3][jj], ahi.y, bd[jj], acc[3][jj]);
            }
        }
        if (p + 1 < P) {
            const int nb = buf ^ 1;
            As[nb][ac + 0][ar] = a0.x; As[nb][ac + 1][ar] = a0.y;
            As[nb][ac + 2][ar] = a0.z; As[nb][ac + 3][ar] = a0.w;
            As[nb][ac + 0][ar + 64] = a1.x; As[nb][ac + 1][ar + 64] = a1.y;
            As[nb][ac + 2][ar + 64] = a1.z; As[nb][ac + 3][ar + 64] = a1.w;
            if (TB) {
                Bs[nb][ac + 0][ar] = bv.x; Bs[nb][ac + 1][ar] = bv.y;
                Bs[nb][ac + 2][ar] = bv.z; Bs[nb][ac + 3][ar] = bv.w;
            } else {
                *(float4*)&Bs[nb][bk][bn] = bv;
            }
            __syncthreads();
            buf = nb;
        }
    }

    const int nn = n0 + (tx << 2);
    float4 bvec;
    if (bias) bvec = *(const float4*)&bias[nn];
    #pragma unroll
    for (int p2 = 0; p2 < 4; p2++) {
        float rlo[4], rhi[4];
        #pragma unroll
        for (int jj = 0; jj < 4; jj++) {
            float lo, hi;
            asm("mov.b64 {%0, %1}, %2;" : "=f"(lo), "=f"(hi) : "l"(acc[p2][jj]));
            rlo[jj] = lo; rhi[jj] = hi;
        }
        #pragma unroll
        for (int half = 0; half < 2; half++) {
            const int mm = m0 + (ty << 3) + (p2 << 1) + half;
            float* rr = half ? rhi : rlo;
            float4 cv;
            cv.x = rr[0] * scale; cv.y = rr[1] * scale;
            cv.z = rr[2] * scale; cv.w = rr[3] * scale;
            if (bias) { cv.x += bvec.x; cv.y += bvec.y; cv.z += bvec.z; cv.w += bvec.w; }
            if (CAUSAL) {
                if (nn + 0 > mm) cv.x = 0.f;
                if (nn + 1 > mm) cv.y = 0.f;
                if (nn + 2 > mm) cv.z = 0.f;
                if (nn + 3 > mm) cv.w = 0.f;
            }
            *(float4*)(C + (size_t)mm * ldc + nn) = cv;
        }
    }
}

// ---------------- small kernels ----------------
__global__ void elu_qk_kernel() {
    int idx = blockIdx.x * blockDim.x + threadIdx.x;
    if (idx >= BT * 1024) return;
    int row = idx >> 10, c = idx & 1023;
    float* p = &g_qkv[(size_t)row * D3 + c];
    float x = *p;
    *p = x > 0.f ? x + 1.f : expf(x);
}

__global__ void den_kernel() {
    __shared__ float sb[32];
    int row = blockIdx.x;
    float s = 0.f;
    for (int c = threadIdx.x; c < TT; c += 256) s += g_S[(size_t)row * TT + c];
    s = block_red_sum(s, sb);
    if (threadIdx.x == 0) g_den[row] = s;
}

__global__ void div_kernel() {
    int idx = blockIdx.x * blockDim.x + threadIdx.x;
    if (idx >= BT * DD) return;
    int row = idx >> 9, j = idx & 511;
    g_comb[(size_t)row * 2048 + 1024 + j] /= (g_den[row] + 1e-6f);
}

__global__ void softmax_kernel() {
    __shared__ float sb[32];
    int row = blockIdx.x;
    float x = g_attn[(size_t)row * MMEM + threadIdx.x];
    float m = block_red_max(x, sb);
    float e = expf(x - m);
    float s = block_red_sum(e, sb);
    g_attn[(size_t)row * MMEM + threadIdx.x] = e / s;
}

// mode 0: out = tanh(LN(in));  mode 1: out = LN(tanh(in))
__global__ void ln_kernel(const float* __restrict__ in, const float* __restrict__ gg,
                          const float* __restrict__ bb, float* __restrict__ out,
                          int ldo, int mode)
{
    __shared__ float sb[32];
    int row = blockIdx.x, tid = threadIdx.x;
    float x0 = in[(size_t)row * DD + tid];
    float x1 = in[(size_t)row * DD + 256 + tid];
    if (mode == 1) { x0 = tanhf(x0); x1 = tanhf(x1); }
    float s  = block_red_sum(x0 + x1, sb);
    float sq = block_red_sum(x0 * x0 + x1 * x1, sb);
    float mean = s * (1.f / 512.f);
    float var  = sq * (1.f / 512.f) - mean * mean;
    float rstd = rsqrtf(var + 1e-5f);
    float y0 = (x0 - mean) * rstd * gg[tid] + bb[tid];
    float y1 = (x1 - mean) * rstd * gg[256 + tid] + bb[256 + tid];
    if (mode == 0) { y0 = tanhf(y0); y1 = tanhf(y1); }
    out[(size_t)row * ldo + tid] = y0;
    out[(size_t)row * ldo + 256 + tid] = y1;
}

__global__ void rownorm_kernel(const float* __restrict__ src) {
    __shared__ float sb[32];
    int row = blockIdx.x, tid = threadIdx.x;
    float x0 = src[(size_t)row * DD + tid];
    float x1 = src[(size_t)row * DD + 256 + tid];
    float ss = block_red_sum(x0 * x0 + x1 * x1, sb);
    float inv = 1.f / fmaxf(sqrtf(ss), 1e-12f);
    g_sw[(size_t)row * DD + tid] = x0 * inv;
    g_sw[(size_t)row * DD + 256 + tid] = x1 * inv;
}

// ---------------- host ----------------
static inline void gemm(const float* A, const float* B, const float* bias, float* C,
                        int M, int N, int K, int lda, int ldb, int ldc,
                        float scale, int batch, long long sA, long long sB, long long sC,
                        bool tb, bool causal)
{
    dim3 grid(N / 64, M / 128, batch);
    if (tb) {
        if (causal)
            gemm_kernel<true, true><<<grid, 256>>>(A, B, bias, C, M, N, K, lda, ldb, ldc, sA, sB, sC, scale);
        else
            gemm_kernel<true, false><<<grid, 256>>>(A, B, bias, C, M, N, K, lda, ldb, ldc, sA, sB, sC, scale);
    } else {
        gemm_kernel<false, false><<<grid, 256>>>(A, B, bias, C, M, N, K, lda, ldb, ldc, sA, sB, sC, scale);
    }
}

extern "C" void kernel_launch(void* const* d_in, const int* in_sizes, int n_in,
                              void* d_out, int out_size)
{
    (void)in_sizes; (void)n_in; (void)out_size;
    const int*   x        = (const int*)d_in[0];
    const float* h_f      = (const float*)d_in[1];
    const float* h_s      = (const float*)d_in[2];
    const float* soma_w   = (const float*)d_in[3];
    const float* fast_wih = (const float*)d_in[4];
    const float* fast_whh = (const float*)d_in[5];
    const float* fast_bih = (const float*)d_in[6];
    const float* fast_bhh = (const float*)d_in[7];
    const float* slow_wih = (const float*)d_in[8];
    const float* slow_whh = (const float*)d_in[9];
    const float* slow_bih = (const float*)d_in[10];
    const float* slow_bhh = (const float*)d_in[11];
    const float* qkv_w    = (const float*)d_in[12];
    const float* qkv_b    = (const float*)d_in[13];
    const float* gate_w   = (const float*)d_in[14];
    const float* gate_b   = (const float*)d_in[15];
    const float* gate_g   = (const float*)d_in[16];
    const float* gate_bb  = (const float*)d_in[17];
    const float* mem_bank = (const float*)d_in[18];
    const float* hip_qw   = (const float*)d_in[19];
    const float* hip_qb   = (const float*)d_in[20];
    const float* axon_w   = (const float*)d_in[21];
    const float* axon_b   = (const float*)d_in[22];
    const float* norm_g   = (const float*)d_in[23];
    const float* norm_b   = (const float*)d_in[24];

    float* out = (float*)d_out;
    float* out_logits  = out;            // [B,T,V]
    float* out_thought = out + 262144;   // [B,T,D]
    float* out_hf      = out + 786432;   // [1,B,D]
    float* out_hs      = out + 787456;   // [1,B,D]

    float *p_table, *p_pf, *p_ps, *p_qkv, *p_S, *p_attn, *p_comb,
          *p_tpre, *p_gatepre, *p_qh, *p_sw;
    cudaGetSymbolAddress((void**)&p_table,   g_table);
    cudaGetSymbolAddress((void**)&p_pf,      g_pf);
    cudaGetSymbolAddress((void**)&p_ps,      g_ps);
    cudaGetSymbolAddress((void**)&p_qkv,     g_qkv);
    cudaGetSymbolAddress((void**)&p_S,       g_S);
    cudaGetSymbolAddress((void**)&p_attn,    g_attn);
    cudaGetSymbolAddress((void**)&p_comb,    g_comb);
    cudaGetSymbolAddress((void**)&p_tpre,    g_tpre);
    cudaGetSymbolAddress((void**)&p_gatepre, g_gatepre);
    cudaGetSymbolAddress((void**)&p_qh,      g_qh);
    cudaGetSymbolAddress((void**)&p_sw,      g_sw);

    // normalized embedding rows for logits
    rownorm_kernel<<<VV, 256>>>(soma_w);

    // fast-GRU input-gate token table: [V,3D] = soma_w @ fast_wih^T + fast_bih
    gemm(soma_w, fast_wih, fast_bih, p_table, 256, 1536, 512, 512, 512, 1536,
         1.f, 1, 0, 0, 0, true, false);

    // reset barrier BEFORE the GRU (keeps fused_gru in the ncu window)
    reset_bar_kernel<<<1, 1>>>();

    // fused pipelined GRUs -> p_f, comb[:,0:512], p_s, hf1, hs1
    fused_gru_kernel<<<FUSE_BLOCKS, GRU_THREADS>>>(
        fast_whh, fast_bhh, slow_wih, slow_bih, slow_whh, slow_bhh,
        p_table, x, h_f, h_s, p_pf, p_comb, p_ps, out_hf, out_hs);

    // projections from p_s
    gemm(p_ps, qkv_w,  qkv_b,  p_qkv,     1024, 1536, 512, 512, 512, 1536, 1.f, 1, 0, 0, 0, true, false);
    gemm(p_ps, gate_w, gate_b, p_gatepre, 1024,  512, 512, 512, 512,  512, 1.f, 1, 0, 0, 0, true, false);
    gemm(p_ps, hip_qw, hip_qb, p_qh,      1024,  512, 512, 512, 512,  512, 1.f, 1, 0, 0, 0, true, false);

    // q,k <- elu+1
    elu_qk_kernel<<<(BT * 1024) / 256, 256>>>();

    // linear attention == causal attention: S = q k^T (masked), per batch
    gemm(p_qkv, p_qkv + 512, nullptr, p_S, 512, 512, 512, 1536, 1536, 512,
         1.f, 2, 512LL * 1536, 512LL * 1536, 512LL * 512, true, true);
    den_kernel<<<BT, 256>>>();
    // num = S @ v -> combined[:, 1024:1536]
    gemm(p_S, p_qkv + 1024, nullptr, p_comb + 1024, 512, 512, 512, 512, 1536, 2048,
         1.f, 2, 512LL * 512, 512LL * 1536, 512LL * 2048, false, false);
    div_kernel<<<(BT * DD) / 256, 256>>>();

    // intent = tanh(LN(gatepre)) -> combined[:, 512:1024]
    ln_kernel<<<BT, 256>>>(p_gatepre, gate_g, gate_bb, p_comb + 512, 2048, 0);

    // hippocampus: attn = softmax(qh @ mem^T / sqrt(D)); episodes = attn @ mem
    gemm(p_qh, mem_bank, nullptr, p_attn, 1024, 256, 512, 512, 512, 256,
         0.044194173824159216f, 1, 0, 0, 0, true, false);
    softmax_kernel<<<BT, 256>>>();
    gemm(p_attn, mem_bank, nullptr, p_comb + 1536, 1024, 512, 256, 256, 512, 2048,
         1.f, 1, 0, 0, 0, false, false);

    // thought = LN(tanh(combined @ axon_w^T + axon_b))
    gemm(p_comb, axon_w, axon_b, p_tpre, 1024, 512, 2048, 2048, 2048, 512,
         1.f, 1, 0, 0, 0, true, false);
    ln_kernel<<<BT, 256>>>(p_tpre, norm_g, norm_b, out_thought, 512, 1);

    // logits = (thought @ sw^T) * 16
    gemm(out_thought, p_sw, nullptr, out_logits, 1024, 256, 512, 512, 512, 256,
         16.f, 1, 0, 0, 0, true, false);
}